// round 1
// baseline (speedup 1.0000x reference)
#include <cuda_runtime.h>
#include <math.h>

#define B_  2
#define N_  2048
#define D_  1024
#define H_  8
#define QH_ 16
#define DH_ 64
#define ROWS (B_*N_)   // 4096

// ---------------- scratch (device globals; no allocs) ----------------
__device__ float g_xn[(size_t)ROWS * D_];            // rmsnormed tokens
__device__ float g_qproj[(size_t)ROWS * 1024];       // x @ Wq
__device__ float g_kv[(size_t)ROWS * 1024];          // x @ Wkv
__device__ float g_q[(size_t)B_ * QH_ * N_ * DH_];   // [b][qh][n][dh]
__device__ float g_k[(size_t)B_ * H_  * N_ * DH_];   // [b][h][n][dh]
__device__ float g_v[(size_t)B_ * H_  * N_ * DH_];   // [b][h][n][dh]
__device__ float g_o[(size_t)B_ * QH_ * N_ * DH_];   // per-qhead attn out
__device__ float g_oc[(size_t)ROWS * (H_ * DH_)];    // group-summed [b*n][512]

// ---------------- 1) RMSNorm ----------------
__global__ __launch_bounds__(256) void k_rmsnorm(const float* __restrict__ x,
                                                 const float* __restrict__ w) {
    int row = blockIdx.x;                       // b*N + n
    const float4* xr = (const float4*)(x + (size_t)row * D_);
    float4 xv = xr[threadIdx.x];
    float ss = xv.x*xv.x + xv.y*xv.y + xv.z*xv.z + xv.w*xv.w;
    #pragma unroll
    for (int o = 16; o; o >>= 1) ss += __shfl_xor_sync(0xffffffffu, ss, o);
    __shared__ float sred[8];
    int wid = threadIdx.x >> 5, lid = threadIdx.x & 31;
    if (lid == 0) sred[wid] = ss;
    __syncthreads();
    if (wid == 0) {
        float v = (lid < 8) ? sred[lid] : 0.0f;
        #pragma unroll
        for (int o = 4; o; o >>= 1) v += __shfl_xor_sync(0xffffffffu, v, o);
        if (lid == 0) sred[0] = v;
    }
    __syncthreads();
    float s = rsqrtf(sred[0] * (1.0f / D_) + 1.192092896e-7f);
    float4 wv = ((const float4*)w)[threadIdx.x];
    float4 y;
    y.x = xv.x * s * wv.x; y.y = xv.y * s * wv.y;
    y.z = xv.z * s * wv.z; y.w = xv.w * s * wv.w;
    ((float4*)(g_xn + (size_t)row * D_))[threadIdx.x] = y;
}

// ---------------- 2) SGEMM 128x128x16, 256 thr, 8x8/thread ----------------
// MODE 0: g_xn @ W -> g_qproj (K=1024)
// MODE 1: g_xn @ W -> g_kv    (K=1024)
// MODE 2: g_oc @ W -> Cext    (K=512)
template <int MODE>
__global__ __launch_bounds__(256) void k_gemm(const float* __restrict__ W,
                                              float* __restrict__ Cext) {
    const int K  = (MODE == 2) ? 512 : 1024;
    const int Nc = 1024;
    const float* A = (MODE == 2) ? g_oc : g_xn;
    float* C = (MODE == 0) ? g_qproj : (MODE == 1) ? g_kv : Cext;

    __shared__ float As[16][128];
    __shared__ float Bs[16][128];

    int t = threadIdx.x;
    int tx = t & 15, ty = t >> 4;
    int m0 = blockIdx.y * 128, n0 = blockIdx.x * 128;

    float acc[8][8];
    #pragma unroll
    for (int i = 0; i < 8; i++)
        #pragma unroll
        for (int j = 0; j < 8; j++) acc[i][j] = 0.0f;

    for (int k0 = 0; k0 < K; k0 += 16) {
        // load A tile 128x16 (transposed into As[k][m])
        #pragma unroll
        for (int rep = 0; rep < 2; rep++) {
            int slot = t + rep * 256;
            int i = slot >> 2;
            int kk = (slot & 3) * 4;
            float4 a = *(const float4*)(A + (size_t)(m0 + i) * K + k0 + kk);
            As[kk + 0][i] = a.x; As[kk + 1][i] = a.y;
            As[kk + 2][i] = a.z; As[kk + 3][i] = a.w;
        }
        // load B tile 16x128
        #pragma unroll
        for (int rep = 0; rep < 2; rep++) {
            int slot = t + rep * 256;
            int kk = slot >> 5;
            int j = (slot & 31) * 4;
            *(float4*)&Bs[kk][j] = *(const float4*)(W + (size_t)(k0 + kk) * Nc + n0 + j);
        }
        __syncthreads();
        #pragma unroll
        for (int kk = 0; kk < 16; kk++) {
            float ra[8], rb[8];
            *(float4*)(ra)     = *(const float4*)&As[kk][ty * 4];
            *(float4*)(ra + 4) = *(const float4*)&As[kk][64 + ty * 4];
            *(float4*)(rb)     = *(const float4*)&Bs[kk][tx * 4];
            *(float4*)(rb + 4) = *(const float4*)&Bs[kk][64 + tx * 4];
            #pragma unroll
            for (int i = 0; i < 8; i++)
                #pragma unroll
                for (int j = 0; j < 8; j++) acc[i][j] = fmaf(ra[i], rb[j], acc[i][j]);
        }
        __syncthreads();
    }
    // write out (split-tile: rows {ty*4+r, 64+ty*4+r}, cols {tx*4.., 64+tx*4..})
    #pragma unroll
    for (int rh = 0; rh < 2; rh++)
        #pragma unroll
        for (int r4 = 0; r4 < 4; r4++) {
            int row = m0 + rh * 64 + ty * 4 + r4;
            int i = rh * 4 + r4;
            #pragma unroll
            for (int ch = 0; ch < 2; ch++) {
                float4 v = make_float4(acc[i][ch*4+0], acc[i][ch*4+1],
                                       acc[i][ch*4+2], acc[i][ch*4+3]);
                *(float4*)(C + (size_t)row * Nc + n0 + ch * 64 + tx * 4) = v;
            }
        }
}

// ---------------- 3) q head norm: l2norm * (gamma+1)*8, transpose ----------------
__global__ __launch_bounds__(256) void k_qnorm(const float* __restrict__ gamma) {
    int warp = threadIdx.x >> 5, lane = threadIdx.x & 31;
    int vec = blockIdx.x * 8 + warp;          // < 65536
    int row = vec >> 4;                       // b*N + n
    int qh  = vec & 15;
    float2 x = *(const float2*)(g_qproj + (size_t)row * 1024 + qh * 64 + lane * 2);
    float ss = x.x * x.x + x.y * x.y;
    #pragma unroll
    for (int o = 16; o; o >>= 1) ss += __shfl_xor_sync(0xffffffffu, ss, o);
    float inv = 1.0f / fmaxf(sqrtf(ss), 1e-12f);
    float2 g = *(const float2*)(gamma + qh * 64 + lane * 2);
    int b = row >> 11, n = row & 2047;
    float2 y;
    y.x = x.x * inv * (g.x + 1.0f) * 8.0f;
    y.y = x.y * inv * (g.y + 1.0f) * 8.0f;
    *(float2*)(g_q + ((((size_t)b * QH_ + qh) * N_ + n) * DH_) + lane * 2) = y;
}

// ---------------- 4) k head norm + v transpose-copy ----------------
__global__ __launch_bounds__(256) void k_knorm(const float* __restrict__ gamma) {
    int warp = threadIdx.x >> 5, lane = threadIdx.x & 31;
    int vec = blockIdx.x * 8 + warp;          // < 32768
    int row = vec >> 3;                       // b*N + n
    int h   = vec & 7;
    const float* base = g_kv + (size_t)row * 1024 + h * 64 + lane * 2;
    float2 kx = *(const float2*)base;
    float2 vx = *(const float2*)(base + 512);
    float ss = kx.x * kx.x + kx.y * kx.y;
    #pragma unroll
    for (int o = 16; o; o >>= 1) ss += __shfl_xor_sync(0xffffffffu, ss, o);
    float inv = 1.0f / fmaxf(sqrtf(ss), 1e-12f);
    float2 g = *(const float2*)(gamma + h * 64 + lane * 2);
    int b = row >> 11, n = row & 2047;
    size_t dst = (((size_t)b * H_ + h) * N_ + n) * DH_ + lane * 2;
    float2 ky;
    ky.x = kx.x * inv * (g.x + 1.0f) * 8.0f;
    ky.y = kx.y * inv * (g.y + 1.0f) * 8.0f;
    *(float2*)(g_k + dst) = ky;
    *(float2*)(g_v + dst) = vx;
}

// ---------------- 5) causal attention, 64x64 tiles, fp32 ----------------
// Softcapped score |s|<=6.25 -> no online max needed, just exp + running sum.
__global__ __launch_bounds__(256) void k_attn() {
    __shared__ float Qs[64 * 64];   // plain, stride 64
    __shared__ float KP[64 * 64];   // XOR-swizzled (K tile, then reused for P)
    __shared__ float Vs[64 * 64];   // plain, stride 64

    int bqh = blockIdx.y;                       // b*16 + qh
    int it  = gridDim.x - 1 - blockIdx.x;       // biggest tiles first
    int b = bqh >> 4, qh = bqh & 15, h = qh >> 1;

    const float* Qg = g_q + (((size_t)bqh) * N_ + it * 64) * DH_;
    const float* Kg = g_k + ((size_t)(b * H_ + h)) * N_ * DH_;
    const float* Vg = g_v + ((size_t)(b * H_ + h)) * N_ * DH_;

    int t = threadIdx.x, tx = t & 15, ty = t >> 4;

    // load Q tile
    #pragma unroll
    for (int rep = 0; rep < 4; rep++) {
        int slot = t + rep * 256;
        int i = slot >> 4, d = (slot & 15) * 4;
        *(float4*)&Qs[i * 64 + d] = *(const float4*)(Qg + i * 64 + d);
    }

    float o[4][4];
    #pragma unroll
    for (int r = 0; r < 4; r++)
        #pragma unroll
        for (int c = 0; c < 4; c++) o[r][c] = 0.0f;
    float lsum[4] = {0.f, 0.f, 0.f, 0.f};

    int ntiles = it + 1;
    for (int jt = 0; jt < ntiles; jt++) {
        __syncthreads();   // prior-iter KP/Vs readers done (also covers Q load)
        // load K (swizzled: key = j>>2) and V tiles
        #pragma unroll
        for (int rep = 0; rep < 4; rep++) {
            int slot = t + rep * 256;
            int j = slot >> 4, d = (slot & 15) * 4;
            int sw = ((((d >> 2) ^ (j >> 2)) & 15) << 2);
            *(float4*)&KP[j * 64 + sw] = *(const float4*)(Kg + (size_t)(jt * 64 + j) * 64 + d);
            *(float4*)&Vs[j * 64 + d]  = *(const float4*)(Vg + (size_t)(jt * 64 + j) * 64 + d);
        }
        __syncthreads();

        // S = Q K^T  (thread owns S[ty*4+r][tx*4+c])
        float s[4][4];
        #pragma unroll
        for (int r = 0; r < 4; r++)
            #pragma unroll
            for (int c = 0; c < 4; c++) s[r][c] = 0.0f;

        #pragma unroll 4
        for (int d4 = 0; d4 < 16; d4++) {
            int off4 = (((d4 ^ tx) & 15) << 2);
            #pragma unroll
            for (int dd = 0; dd < 4; dd++) {
                int d = d4 * 4 + dd;
                float qa[4], kb[4];
                #pragma unroll
                for (int r = 0; r < 4; r++) qa[r] = Qs[(ty * 4 + r) * 64 + d];
                #pragma unroll
                for (int c = 0; c < 4; c++) kb[c] = KP[(tx * 4 + c) * 64 + off4 + dd];
                #pragma unroll
                for (int r = 0; r < 4; r++)
                    #pragma unroll
                    for (int c = 0; c < 4; c++) s[r][c] = fmaf(qa[r], kb[c], s[r][c]);
            }
        }
        __syncthreads();   // all K reads done before P overwrites KP

        bool diag = (jt == it);
        int i0g = it * 64, j0g = jt * 64;
        #pragma unroll
        for (int r = 0; r < 4; r++) {
            int iglob = i0g + ty * 4 + r;
            float rowsum = 0.0f;
            #pragma unroll
            for (int c = 0; c < 4; c++) {
                float v = tanhf(s[r][c] * (1.0f / 50.0f)) * 6.25f; // *50 * dh^-0.5
                float p = __expf(v);
                if (diag && (j0g + tx * 4 + c > iglob)) p = 0.0f;
                s[r][c] = p;
                rowsum += p;
            }
            rowsum += __shfl_xor_sync(0xffffffffu, rowsum, 1);
            rowsum += __shfl_xor_sync(0xffffffffu, rowsum, 2);
            rowsum += __shfl_xor_sync(0xffffffffu, rowsum, 4);
            rowsum += __shfl_xor_sync(0xffffffffu, rowsum, 8);
            lsum[r] += rowsum;
            // store P row (swizzle key = i>>2 == ty)
            int i = ty * 4 + r;
            *(float4*)&KP[i * 64 + (((tx ^ ty) & 15) << 2)] =
                make_float4(s[r][0], s[r][1], s[r][2], s[r][3]);
        }
        __syncthreads();

        // O += P @ V  (thread owns O[ty*4+r][tx*4+c])
        #pragma unroll 4
        for (int j4 = 0; j4 < 16; j4++) {
            int offp4 = (((j4 ^ ty) & 15) << 2);
            #pragma unroll
            for (int jj = 0; jj < 4; jj++) {
                int j = j4 * 4 + jj;
                float pv[4];
                #pragma unroll
                for (int r = 0; r < 4; r++) pv[r] = KP[(ty * 4 + r) * 64 + offp4 + jj];
                float4 vv = *(const float4*)&Vs[j * 64 + tx * 4];
                #pragma unroll
                for (int r = 0; r < 4; r++) {
                    o[r][0] = fmaf(pv[r], vv.x, o[r][0]);
                    o[r][1] = fmaf(pv[r], vv.y, o[r][1]);
                    o[r][2] = fmaf(pv[r], vv.z, o[r][2]);
                    o[r][3] = fmaf(pv[r], vv.w, o[r][3]);
                }
            }
        }
    }

    float* Og = g_o + (((size_t)bqh) * N_ + it * 64) * DH_;
    #pragma unroll
    for (int r = 0; r < 4; r++) {
        float inv = 1.0f / lsum[r];
        float4 ov = make_float4(o[r][0] * inv, o[r][1] * inv,
                                o[r][2] * inv, o[r][3] * inv);
        *(float4*)(Og + (ty * 4 + r) * 64 + tx * 4) = ov;
    }
}

// ---------------- 6) group-sum combine: oc[b,n,h*64+d] = o[2h] + o[2h+1] ----------------
__global__ __launch_bounds__(256) void k_combine() {
    int s4 = blockIdx.x * 256 + threadIdx.x;   // float4 slot, < 524288
    int col = (s4 & 127) * 4;                  // 0..511
    int row = s4 >> 7;                         // b*N + n
    int h = col >> 6, dh = col & 63;
    int b = row >> 11, n = row & 2047;
    const float* o1 = g_o + ((((size_t)b * QH_ + 2 * h) * N_ + n) * DH_ + dh);
    const float* o2 = o1 + (size_t)N_ * DH_;
    float4 a = *(const float4*)o1, c = *(const float4*)o2;
    float4 y = make_float4(a.x + c.x, a.y + c.y, a.z + c.z, a.w + c.w);
    *(float4*)(g_oc + (size_t)row * 512 + col) = y;
}

// ---------------- launch ----------------
extern "C" void kernel_launch(void* const* d_in, const int* in_sizes, int n_in,
                              void* d_out, int out_size) {
    const float* tokens  = (const float*)d_in[0];
    const float* norm_w  = (const float*)d_in[1];
    const float* Wq      = (const float*)d_in[2];
    const float* Wkv     = (const float*)d_in[3];
    const float* Wout    = (const float*)d_in[4];
    const float* q_gamma = (const float*)d_in[5];
    const float* k_gamma = (const float*)d_in[6];
    float* out = (float*)d_out;

    k_rmsnorm<<<ROWS, 256>>>(tokens, norm_w);
    k_gemm<0><<<dim3(8, 32), 256>>>(Wq, nullptr);
    k_gemm<1><<<dim3(8, 32), 256>>>(Wkv, nullptr);
    k_qnorm<<<8192, 256>>>(q_gamma);
    k_knorm<<<4096, 256>>>(k_gamma);
    k_attn<<<dim3(32, 32), 256>>>();
    k_combine<<<2048, 256>>>();
    k_gemm<2><<<dim3(8, 32), 256>>>(Wout, out);
}

// round 3
// speedup vs baseline: 1.3812x; 1.3812x over previous
#include <cuda_runtime.h>
#include <cstdint>
#include <math.h>

#define B_  2
#define N_  2048
#define D_  1024
#define H_  8
#define QH_ 16
#define DH_ 64
#define ROWS (B_*N_)   // 4096

// ---------------- scratch (device globals; no allocs) ----------------
__device__ float g_xn[(size_t)ROWS * D_];            // rmsnormed tokens (tf32-rounded)
__device__ float g_qproj[(size_t)ROWS * 1024];       // x @ Wq
__device__ float g_kv[(size_t)ROWS * 1024];          // x @ Wkv
__device__ float g_q[(size_t)B_ * QH_ * N_ * DH_];   // [b][qh][n][dh]
__device__ float g_k[(size_t)B_ * H_  * N_ * DH_];   // [b][h][n][dh]
__device__ float g_v[(size_t)B_ * H_  * N_ * DH_];   // [b][h][n][dh]
__device__ float g_o[(size_t)B_ * QH_ * N_ * DH_];   // per-qhead attn out
__device__ float g_oc[(size_t)ROWS * (H_ * DH_)];    // group-summed (tf32-rounded)
__device__ float g_Wqr [(size_t)1024 * 1024];        // tf32-rounded Wq  [k][n]
__device__ float g_Wkvr[(size_t)1024 * 1024];        // tf32-rounded Wkv [k][n]
__device__ float g_Wor [(size_t)512 * 1024];         // tf32-rounded Wout[k][n]

// ---------------- helpers ----------------
__device__ __forceinline__ float tf32r(float x) {
    uint32_t u;
    asm("cvt.rna.tf32.f32 %0, %1;" : "=r"(u) : "f"(x));
    return __uint_as_float(u);
}
__device__ __forceinline__ uint32_t smem_u32(const void* p) {
    uint32_t a;
    asm("{ .reg .u64 t; cvta.to.shared.u64 t, %1; cvt.u32.u64 %0, t; }" : "=r"(a) : "l"(p));
    return a;
}
__device__ __forceinline__ void cpa16(uint32_t dst, const float* src) {
    asm volatile("cp.async.ca.shared.global [%0], [%1], 16;" :: "r"(dst), "l"(src));
}
#define CP_COMMIT() asm volatile("cp.async.commit_group;" ::: "memory")
#define CP_WAIT(n)  asm volatile("cp.async.wait_group %0;" :: "n"(n) : "memory")

// mma.sync m16n8k8 tf32: d += a*b
__device__ __forceinline__ void mma8(float* d, const float* a, const float* b) {
    asm volatile("mma.sync.aligned.m16n8k8.row.col.f32.tf32.tf32.f32 "
                 "{%0,%1,%2,%3}, {%4,%5,%6,%7}, {%8,%9}, {%0,%1,%2,%3};"
                 : "+f"(d[0]), "+f"(d[1]), "+f"(d[2]), "+f"(d[3])
                 : "r"(__float_as_uint(a[0])), "r"(__float_as_uint(a[1])),
                   "r"(__float_as_uint(a[2])), "r"(__float_as_uint(a[3])),
                   "r"(__float_as_uint(b[0])), "r"(__float_as_uint(b[1])));
}

// ---------------- 1) RMSNorm (tf32-rounded output) ----------------
__global__ __launch_bounds__(256) void k_rmsnorm(const float* __restrict__ x,
                                                 const float* __restrict__ w) {
    int row = blockIdx.x;
    const float4* xr = (const float4*)(x + (size_t)row * D_);
    float4 xv = xr[threadIdx.x];
    float ss = xv.x*xv.x + xv.y*xv.y + xv.z*xv.z + xv.w*xv.w;
    #pragma unroll
    for (int o = 16; o; o >>= 1) ss += __shfl_xor_sync(0xffffffffu, ss, o);
    __shared__ float sred[8];
    int wid = threadIdx.x >> 5, lid = threadIdx.x & 31;
    if (lid == 0) sred[wid] = ss;
    __syncthreads();
    if (wid == 0) {
        float v = (lid < 8) ? sred[lid] : 0.0f;
        #pragma unroll
        for (int o = 4; o; o >>= 1) v += __shfl_xor_sync(0xffffffffu, v, o);
        if (lid == 0) sred[0] = v;
    }
    __syncthreads();
    float s = rsqrtf(sred[0] * (1.0f / D_) + 1.192092896e-7f);
    float4 wv = ((const float4*)w)[threadIdx.x];
    float4 y;
    y.x = tf32r(xv.x * s * wv.x); y.y = tf32r(xv.y * s * wv.y);
    y.z = tf32r(xv.z * s * wv.z); y.w = tf32r(xv.w * s * wv.w);
    ((float4*)(g_xn + (size_t)row * D_))[threadIdx.x] = y;
}

// ---------------- 2) elementwise tf32 round of weights ----------------
__global__ __launch_bounds__(256) void k_round(const float4* __restrict__ src,
                                               float4* __restrict__ dst, int n4) {
    int i = blockIdx.x * 256 + threadIdx.x;
    if (i < n4) {
        float4 v = src[i];
        v.x = tf32r(v.x); v.y = tf32r(v.y); v.z = tf32r(v.z); v.w = tf32r(v.w);
        dst[i] = v;
    }
}

// ---------------- 3) tf32 mma.sync GEMM: C[m][n] = sum_k A[m][k] W[k][n] ----------------
// CTA 128x128, 8 warps (2x4), warp tile 64x32, K-chunk 16, cp.async double buffer.
#define ASTRIDE 20
#define BSTRIDE 136
#define ASZ (128 * ASTRIDE)     // floats
#define BSZ (16 * BSTRIDE)      // floats
#define STAGE (ASZ + BSZ)

__global__ __launch_bounds__(256) void k_mmagemm(const float* __restrict__ A,
                                                 const float* __restrict__ W,
                                                 float* __restrict__ C, int K) {
    __shared__ float smem[2 * STAGE];
    const int t = threadIdx.x, wid = t >> 5, lane = t & 31;
    const int wm = wid >> 2, wn = wid & 3;
    const int r = lane >> 2, cq = lane & 3;
    const int m0 = blockIdx.y * 128, n0 = blockIdx.x * 128;
    const uint32_t sb = smem_u32(smem);

    // per-thread load slots (2 A chunks + 2 B chunks per stage)
    const int qa0 = t, qa1 = t + 256;          // A chunk ids 0..511
    const int ar0 = qa0 >> 2, ak0 = (qa0 & 3) * 4;
    const int ar1 = qa1 >> 2, ak1 = (qa1 & 3) * 4;
    const int qb0 = t, qb1 = t + 256;          // B chunk ids 0..511
    const int bk0 = qb0 >> 5, bj0 = (qb0 & 31) * 4;
    const int bk1 = qb1 >> 5, bj1 = (qb1 & 31) * 4;

    float d[4][4][4];
    #pragma unroll
    for (int i = 0; i < 4; i++)
        #pragma unroll
        for (int j = 0; j < 4; j++)
            #pragma unroll
            for (int v = 0; v < 4; v++) d[i][j][v] = 0.0f;

    const int nc = K >> 4;

    #define LOAD_STAGE(s, c) do { \
        uint32_t ab = sb + (s) * (STAGE * 4); \
        uint32_t bb = ab + ASZ * 4; \
        int k0 = (c) << 4; \
        cpa16(ab + (ar0 * ASTRIDE + ak0) * 4, A + (size_t)(m0 + ar0) * K + k0 + ak0); \
        cpa16(ab + (ar1 * ASTRIDE + ak1) * 4, A + (size_t)(m0 + ar1) * K + k0 + ak1); \
        cpa16(bb + (bk0 * BSTRIDE + bj0) * 4, W + (size_t)(k0 + bk0) * 1024 + n0 + bj0); \
        cpa16(bb + (bk1 * BSTRIDE + bj1) * 4, W + (size_t)(k0 + bk1) * 1024 + n0 + bj1); \
        CP_COMMIT(); \
    } while (0)

    LOAD_STAGE(0, 0);

    for (int c = 0; c < nc; c++) {
        int s = c & 1;
        if (c + 1 < nc) { LOAD_STAGE(s ^ 1, c + 1); CP_WAIT(1); }
        else            { CP_WAIT(0); }
        __syncthreads();

        const float* As_ = smem + s * STAGE;
        const float* Bs_ = As_ + ASZ;
        #pragma unroll
        for (int ks = 0; ks < 2; ks++) {
            int kc = ks * 8 + cq;
            float a[4][4], b[4][2];
            #pragma unroll
            for (int mt = 0; mt < 4; mt++) {
                const float* ap = As_ + (wm * 64 + mt * 16 + r) * ASTRIDE;
                a[mt][0] = ap[kc];
                a[mt][1] = ap[8 * ASTRIDE + kc];
                a[mt][2] = ap[kc + 4];
                a[mt][3] = ap[8 * ASTRIDE + kc + 4];
            }
            #pragma unroll
            for (int nt = 0; nt < 4; nt++) {
                int n = wn * 32 + nt * 8 + r;
                b[nt][0] = Bs_[kc * BSTRIDE + n];
                b[nt][1] = Bs_[(kc + 4) * BSTRIDE + n];
            }
            #pragma unroll
            for (int mt = 0; mt < 4; mt++)
                #pragma unroll
                for (int nt = 0; nt < 4; nt++) mma8(d[mt][nt], a[mt], b[nt]);
        }
        __syncthreads();
    }

    // epilogue
    #pragma unroll
    for (int mt = 0; mt < 4; mt++) {
        int row = m0 + wm * 64 + mt * 16 + r;
        #pragma unroll
        for (int nt = 0; nt < 4; nt++) {
            int col = n0 + wn * 32 + nt * 8 + 2 * cq;
            *(float2*)(C + (size_t)row * 1024 + col) = make_float2(d[mt][nt][0], d[mt][nt][1]);
            *(float2*)(C + (size_t)(row + 8) * 1024 + col) = make_float2(d[mt][nt][2], d[mt][nt][3]);
        }
    }
    #undef LOAD_STAGE
}

// ---------------- 4) q head norm ----------------
__global__ __launch_bounds__(256) void k_qnorm(const float* __restrict__ gamma) {
    int warp = threadIdx.x >> 5, lane = threadIdx.x & 31;
    int vec = blockIdx.x * 8 + warp;
    int row = vec >> 4;
    int qh  = vec & 15;
    float2 x = *(const float2*)(g_qproj + (size_t)row * 1024 + qh * 64 + lane * 2);
    float ss = x.x * x.x + x.y * x.y;
    #pragma unroll
    for (int o = 16; o; o >>= 1) ss += __shfl_xor_sync(0xffffffffu, ss, o);
    float inv = 1.0f / fmaxf(sqrtf(ss), 1e-12f);
    float2 g = *(const float2*)(gamma + qh * 64 + lane * 2);
    int b = row >> 11, n = row & 2047;
    float2 y;
    y.x = x.x * inv * (g.x + 1.0f) * 8.0f;
    y.y = x.y * inv * (g.y + 1.0f) * 8.0f;
    *(float2*)(g_q + ((((size_t)b * QH_ + qh) * N_ + n) * DH_) + lane * 2) = y;
}

// ---------------- 5) k head norm + v transpose-copy ----------------
__global__ __launch_bounds__(256) void k_knorm(const float* __restrict__ gamma) {
    int warp = threadIdx.x >> 5, lane = threadIdx.x & 31;
    int vec = blockIdx.x * 8 + warp;
    int row = vec >> 3;
    int h   = vec & 7;
    const float* base = g_kv + (size_t)row * 1024 + h * 64 + lane * 2;
    float2 kx = *(const float2*)base;
    float2 vx = *(const float2*)(base + 512);
    float ss = kx.x * kx.x + kx.y * kx.y;
    #pragma unroll
    for (int o = 16; o; o >>= 1) ss += __shfl_xor_sync(0xffffffffu, ss, o);
    float inv = 1.0f / fmaxf(sqrtf(ss), 1e-12f);
    float2 g = *(const float2*)(gamma + h * 64 + lane * 2);
    int b = row >> 11, n = row & 2047;
    size_t dst = (((size_t)b * H_ + h) * N_ + n) * DH_ + lane * 2;
    float2 ky;
    ky.x = kx.x * inv * (g.x + 1.0f) * 8.0f;
    ky.y = kx.y * inv * (g.y + 1.0f) * 8.0f;
    *(float2*)(g_k + dst) = ky;
    *(float2*)(g_v + dst) = vx;
}

// ---------------- 6) causal attention, 64x64 tiles, fp32 ----------------
__global__ __launch_bounds__(256) void k_attn() {
    __shared__ float Qs[64 * 64];
    __shared__ float KP[64 * 64];   // XOR-swizzled (K tile, then reused for P)
    __shared__ float Vs[64 * 64];

    int bqh = blockIdx.y;
    int it  = gridDim.x - 1 - blockIdx.x;
    int b = bqh >> 4, qh = bqh & 15, h = qh >> 1;

    const float* Qg = g_q + (((size_t)bqh) * N_ + it * 64) * DH_;
    const float* Kg = g_k + ((size_t)(b * H_ + h)) * N_ * DH_;
    const float* Vg = g_v + ((size_t)(b * H_ + h)) * N_ * DH_;

    int t = threadIdx.x, tx = t & 15, ty = t >> 4;

    #pragma unroll
    for (int rep = 0; rep < 4; rep++) {
        int slot = t + rep * 256;
        int i = slot >> 4, d = (slot & 15) * 4;
        *(float4*)&Qs[i * 64 + d] = *(const float4*)(Qg + i * 64 + d);
    }

    float o[4][4];
    #pragma unroll
    for (int r = 0; r < 4; r++)
        #pragma unroll
        for (int c = 0; c < 4; c++) o[r][c] = 0.0f;
    float lsum[4] = {0.f, 0.f, 0.f, 0.f};

    int ntiles = it + 1;
    for (int jt = 0; jt < ntiles; jt++) {
        __syncthreads();
        #pragma unroll
        for (int rep = 0; rep < 4; rep++) {
            int slot = t + rep * 256;
            int j = slot >> 4, d = (slot & 15) * 4;
            int sw = ((((d >> 2) ^ (j >> 2)) & 15) << 2);
            *(float4*)&KP[j * 64 + sw] = *(const float4*)(Kg + (size_t)(jt * 64 + j) * 64 + d);
            *(float4*)&Vs[j * 64 + d]  = *(const float4*)(Vg + (size_t)(jt * 64 + j) * 64 + d);
        }
        __syncthreads();

        float s[4][4];
        #pragma unroll
        for (int r = 0; r < 4; r++)
            #pragma unroll
            for (int c = 0; c < 4; c++) s[r][c] = 0.0f;

        #pragma unroll 4
        for (int d4 = 0; d4 < 16; d4++) {
            int off4 = (((d4 ^ tx) & 15) << 2);
            #pragma unroll
            for (int dd = 0; dd < 4; dd++) {
                int d = d4 * 4 + dd;
                float qa[4], kb[4];
                #pragma unroll
                for (int r = 0; r < 4; r++) qa[r] = Qs[(ty * 4 + r) * 64 + d];
                #pragma unroll
                for (int c = 0; c < 4; c++) kb[c] = KP[(tx * 4 + c) * 64 + off4 + dd];
                #pragma unroll
                for (int r = 0; r < 4; r++)
                    #pragma unroll
                    for (int c = 0; c < 4; c++) s[r][c] = fmaf(qa[r], kb[c], s[r][c]);
            }
        }
        __syncthreads();

        bool diag = (jt == it);
        int i0g = it * 64, j0g = jt * 64;
        #pragma unroll
        for (int r = 0; r < 4; r++) {
            int iglob = i0g + ty * 4 + r;
            float rowsum = 0.0f;
            #pragma unroll
            for (int c = 0; c < 4; c++) {
                float v = tanhf(s[r][c] * (1.0f / 50.0f)) * 6.25f;
                float p = __expf(v);
                if (diag && (j0g + tx * 4 + c > iglob)) p = 0.0f;
                s[r][c] = p;
                rowsum += p;
            }
            rowsum += __shfl_xor_sync(0xffffffffu, rowsum, 1);
            rowsum += __shfl_xor_sync(0xffffffffu, rowsum, 2);
            rowsum += __shfl_xor_sync(0xffffffffu, rowsum, 4);
            rowsum += __shfl_xor_sync(0xffffffffu, rowsum, 8);
            lsum[r] += rowsum;
            int i = ty * 4 + r;
            *(float4*)&KP[i * 64 + (((tx ^ ty) & 15) << 2)] =
                make_float4(s[r][0], s[r][1], s[r][2], s[r][3]);
        }
        __syncthreads();

        #pragma unroll 4
        for (int j4 = 0; j4 < 16; j4++) {
            int offp4 = (((j4 ^ ty) & 15) << 2);
            #pragma unroll
            for (int jj = 0; jj < 4; jj++) {
                int j = j4 * 4 + jj;
                float pv[4];
                #pragma unroll
                for (int r = 0; r < 4; r++) pv[r] = KP[(ty * 4 + r) * 64 + offp4 + jj];
                float4 vv = *(const float4*)&Vs[j * 64 + tx * 4];
                #pragma unroll
                for (int r = 0; r < 4; r++) {
                    o[r][0] = fmaf(pv[r], vv.x, o[r][0]);
                    o[r][1] = fmaf(pv[r], vv.y, o[r][1]);
                    o[r][2] = fmaf(pv[r], vv.z, o[r][2]);
                    o[r][3] = fmaf(pv[r], vv.w, o[r][3]);
                }
            }
        }
    }

    float* Og = g_o + (((size_t)bqh) * N_ + it * 64) * DH_;
    #pragma unroll
    for (int r = 0; r < 4; r++) {
        float inv = 1.0f / lsum[r];
        float4 ov = make_float4(o[r][0] * inv, o[r][1] * inv,
                                o[r][2] * inv, o[r][3] * inv);
        *(float4*)(Og + (ty * 4 + r) * 64 + tx * 4) = ov;
    }
}

// ---------------- 7) group-sum combine (tf32-rounded) ----------------
__global__ __launch_bounds__(256) void k_combine() {
    int s4 = blockIdx.x * 256 + threadIdx.x;
    int col = (s4 & 127) * 4;
    int row = s4 >> 7;
    int h = col >> 6, dh = col & 63;
    int b = row >> 11, n = row & 2047;
    const float* o1 = g_o + ((((size_t)b * QH_ + 2 * h) * N_ + n) * DH_ + dh);
    const float* o2 = o1 + (size_t)N_ * DH_;
    float4 a = *(const float4*)o1, c = *(const float4*)o2;
    float4 y = make_float4(tf32r(a.x + c.x), tf32r(a.y + c.y),
                           tf32r(a.z + c.z), tf32r(a.w + c.w));
    *(float4*)(g_oc + (size_t)row * 512 + col) = y;
}

// ---------------- launch ----------------
extern "C" void kernel_launch(void* const* d_in, const int* in_sizes, int n_in,
                              void* d_out, int out_size) {
    const float* tokens  = (const float*)d_in[0];
    const float* norm_w  = (const float*)d_in[1];
    const float* Wq      = (const float*)d_in[2];
    const float* Wkv     = (const float*)d_in[3];
    const float* Wout    = (const float*)d_in[4];
    const float* q_gamma = (const float*)d_in[5];
    const float* k_gamma = (const float*)d_in[6];
    float* out = (float*)d_out;

    static float *Wqr_p = nullptr, *Wkvr_p = nullptr, *Wor_p = nullptr;
    static float *xn_p = nullptr, *oc_p = nullptr, *qproj_p = nullptr, *kv_p = nullptr;
    if (!Wqr_p) {   // first call is the non-captured correctness run
        cudaGetSymbolAddress((void**)&Wqr_p, g_Wqr);
        cudaGetSymbolAddress((void**)&Wkvr_p, g_Wkvr);
        cudaGetSymbolAddress((void**)&Wor_p, g_Wor);
        cudaGetSymbolAddress((void**)&xn_p, g_xn);
        cudaGetSymbolAddress((void**)&oc_p, g_oc);
        cudaGetSymbolAddress((void**)&qproj_p, g_qproj);
        cudaGetSymbolAddress((void**)&kv_p, g_kv);
    }

    k_rmsnorm<<<ROWS, 256>>>(tokens, norm_w);
    k_round<<<1024, 256>>>((const float4*)Wq,   (float4*)Wqr_p,  262144);
    k_round<<<1024, 256>>>((const float4*)Wkv,  (float4*)Wkvr_p, 262144);
    k_round<<<512,  256>>>((const float4*)Wout, (float4*)Wor_p,  131072);
    k_mmagemm<<<dim3(8, 32), 256>>>(xn_p, Wqr_p,  qproj_p, 1024);
    k_mmagemm<<<dim3(8, 32), 256>>>(xn_p, Wkvr_p, kv_p,    1024);
    k_qnorm<<<8192, 256>>>(q_gamma);
    k_knorm<<<4096, 256>>>(k_gamma);
    k_attn<<<dim3(32, 32), 256>>>();
    k_combine<<<2048, 256>>>();
    k_mmagemm<<<dim3(8, 32), 256>>>(oc_p, Wor_p, out, 512);
}

// round 4
// speedup vs baseline: 2.3749x; 1.7195x over previous
#include <cuda_runtime.h>
#include <cstdint>
#include <math.h>

#define B_  2
#define N_  2048
#define D_  1024
#define H_  8
#define QH_ 16
#define DH_ 64
#define ROWS (B_*N_)   // 4096

// ---------------- scratch (device globals; no allocs) ----------------
__device__ float g_xn[(size_t)ROWS * D_];            // rmsnormed tokens (tf32-rounded)
__device__ float g_qproj[(size_t)ROWS * 1024];       // x @ Wq
__device__ float g_kv[(size_t)ROWS * 1024];          // x @ Wkv
__device__ float g_q[(size_t)B_ * QH_ * N_ * DH_];   // [b][qh][n][dh] tf32
__device__ float g_k[(size_t)B_ * H_  * N_ * DH_];   // [b][h][n][dh] tf32
__device__ float g_v[(size_t)B_ * H_  * N_ * DH_];   // [b][h][n][dh] tf32
__device__ float g_o[(size_t)B_ * QH_ * N_ * DH_];   // per-qhead attn out
__device__ float g_oc[(size_t)ROWS * (H_ * DH_)];    // group-summed (tf32-rounded)
__device__ float g_Wqr [(size_t)1024 * 1024];        // tf32-rounded Wq  [k][n]
__device__ float g_Wkvr[(size_t)1024 * 1024];        // tf32-rounded Wkv [k][n]
__device__ float g_Wor [(size_t)512 * 1024];         // tf32-rounded Wout[k][n]

// ---------------- helpers ----------------
__device__ __forceinline__ float tf32r(float x) {
    uint32_t u;
    asm("cvt.rna.tf32.f32 %0, %1;" : "=r"(u) : "f"(x));
    return __uint_as_float(u);
}
__device__ __forceinline__ uint32_t smem_u32(const void* p) {
    uint32_t a;
    asm("{ .reg .u64 t; cvta.to.shared.u64 t, %1; cvt.u32.u64 %0, t; }" : "=r"(a) : "l"(p));
    return a;
}
__device__ __forceinline__ void cpa16(uint32_t dst, const float* src) {
    asm volatile("cp.async.ca.shared.global [%0], [%1], 16;" :: "r"(dst), "l"(src));
}
#define CP_COMMIT() asm volatile("cp.async.commit_group;" ::: "memory")
#define CP_WAIT(n)  asm volatile("cp.async.wait_group %0;" :: "n"(n) : "memory")

// mma.sync m16n8k8 tf32: d += a*b
__device__ __forceinline__ void mma8(float* d, const float* a, const float* b) {
    asm volatile("mma.sync.aligned.m16n8k8.row.col.f32.tf32.tf32.f32 "
                 "{%0,%1,%2,%3}, {%4,%5,%6,%7}, {%8,%9}, {%0,%1,%2,%3};"
                 : "+f"(d[0]), "+f"(d[1]), "+f"(d[2]), "+f"(d[3])
                 : "r"(__float_as_uint(a[0])), "r"(__float_as_uint(a[1])),
                   "r"(__float_as_uint(a[2])), "r"(__float_as_uint(a[3])),
                   "r"(__float_as_uint(b[0])), "r"(__float_as_uint(b[1])));
}

// ---------------- 1) RMSNorm (tf32-rounded output) ----------------
__global__ __launch_bounds__(256) void k_rmsnorm(const float* __restrict__ x,
                                                 const float* __restrict__ w) {
    int row = blockIdx.x;
    const float4* xr = (const float4*)(x + (size_t)row * D_);
    float4 xv = xr[threadIdx.x];
    float ss = xv.x*xv.x + xv.y*xv.y + xv.z*xv.z + xv.w*xv.w;
    #pragma unroll
    for (int o = 16; o; o >>= 1) ss += __shfl_xor_sync(0xffffffffu, ss, o);
    __shared__ float sred[8];
    int wid = threadIdx.x >> 5, lid = threadIdx.x & 31;
    if (lid == 0) sred[wid] = ss;
    __syncthreads();
    if (wid == 0) {
        float v = (lid < 8) ? sred[lid] : 0.0f;
        #pragma unroll
        for (int o = 4; o; o >>= 1) v += __shfl_xor_sync(0xffffffffu, v, o);
        if (lid == 0) sred[0] = v;
    }
    __syncthreads();
    float s = rsqrtf(sred[0] * (1.0f / D_) + 1.192092896e-7f);
    float4 wv = ((const float4*)w)[threadIdx.x];
    float4 y;
    y.x = tf32r(xv.x * s * wv.x); y.y = tf32r(xv.y * s * wv.y);
    y.z = tf32r(xv.z * s * wv.z); y.w = tf32r(xv.w * s * wv.w);
    ((float4*)(g_xn + (size_t)row * D_))[threadIdx.x] = y;
}

// ---------------- 2) elementwise tf32 round of weights ----------------
__global__ __launch_bounds__(256) void k_round(const float4* __restrict__ src,
                                               float4* __restrict__ dst, int n4) {
    int i = blockIdx.x * 256 + threadIdx.x;
    if (i < n4) {
        float4 v = src[i];
        v.x = tf32r(v.x); v.y = tf32r(v.y); v.z = tf32r(v.z); v.w = tf32r(v.w);
        dst[i] = v;
    }
}

// ---------------- 3) tf32 mma.sync GEMM (proven in R3) ----------------
#define ASTRIDE 20
#define BSTRIDE 136
#define ASZ (128 * ASTRIDE)
#define BSZ (16 * BSTRIDE)
#define STAGE (ASZ + BSZ)

__global__ __launch_bounds__(256) void k_mmagemm(const float* __restrict__ A,
                                                 const float* __restrict__ W,
                                                 float* __restrict__ C, int K) {
    __shared__ float smem[2 * STAGE];
    const int t = threadIdx.x, wid = t >> 5, lane = t & 31;
    const int wm = wid >> 2, wn = wid & 3;
    const int r = lane >> 2, cq = lane & 3;
    const int m0 = blockIdx.y * 128, n0 = blockIdx.x * 128;
    const uint32_t sb = smem_u32(smem);

    const int qa0 = t, qa1 = t + 256;
    const int ar0 = qa0 >> 2, ak0 = (qa0 & 3) * 4;
    const int ar1 = qa1 >> 2, ak1 = (qa1 & 3) * 4;
    const int qb0 = t, qb1 = t + 256;
    const int bk0 = qb0 >> 5, bj0 = (qb0 & 31) * 4;
    const int bk1 = qb1 >> 5, bj1 = (qb1 & 31) * 4;

    float d[4][4][4];
    #pragma unroll
    for (int i = 0; i < 4; i++)
        #pragma unroll
        for (int j = 0; j < 4; j++)
            #pragma unroll
            for (int v = 0; v < 4; v++) d[i][j][v] = 0.0f;

    const int nc = K >> 4;

    #define LOAD_STAGE(s, c) do { \
        uint32_t ab = sb + (s) * (STAGE * 4); \
        uint32_t bb = ab + ASZ * 4; \
        int k0 = (c) << 4; \
        cpa16(ab + (ar0 * ASTRIDE + ak0) * 4, A + (size_t)(m0 + ar0) * K + k0 + ak0); \
        cpa16(ab + (ar1 * ASTRIDE + ak1) * 4, A + (size_t)(m0 + ar1) * K + k0 + ak1); \
        cpa16(bb + (bk0 * BSTRIDE + bj0) * 4, W + (size_t)(k0 + bk0) * 1024 + n0 + bj0); \
        cpa16(bb + (bk1 * BSTRIDE + bj1) * 4, W + (size_t)(k0 + bk1) * 1024 + n0 + bj1); \
        CP_COMMIT(); \
    } while (0)

    LOAD_STAGE(0, 0);

    for (int c = 0; c < nc; c++) {
        int s = c & 1;
        if (c + 1 < nc) { LOAD_STAGE(s ^ 1, c + 1); CP_WAIT(1); }
        else            { CP_WAIT(0); }
        __syncthreads();

        const float* As_ = smem + s * STAGE;
        const float* Bs_ = As_ + ASZ;
        #pragma unroll
        for (int ks = 0; ks < 2; ks++) {
            int kc = ks * 8 + cq;
            float a[4][4], b[4][2];
            #pragma unroll
            for (int mt = 0; mt < 4; mt++) {
                const float* ap = As_ + (wm * 64 + mt * 16 + r) * ASTRIDE;
                a[mt][0] = ap[kc];
                a[mt][1] = ap[8 * ASTRIDE + kc];
                a[mt][2] = ap[kc + 4];
                a[mt][3] = ap[8 * ASTRIDE + kc + 4];
            }
            #pragma unroll
            for (int nt = 0; nt < 4; nt++) {
                int n = wn * 32 + nt * 8 + r;
                b[nt][0] = Bs_[kc * BSTRIDE + n];
                b[nt][1] = Bs_[(kc + 4) * BSTRIDE + n];
            }
            #pragma unroll
            for (int mt = 0; mt < 4; mt++)
                #pragma unroll
                for (int nt = 0; nt < 4; nt++) mma8(d[mt][nt], a[mt], b[nt]);
        }
        __syncthreads();
    }

    #pragma unroll
    for (int mt = 0; mt < 4; mt++) {
        int row = m0 + wm * 64 + mt * 16 + r;
        #pragma unroll
        for (int nt = 0; nt < 4; nt++) {
            int col = n0 + wn * 32 + nt * 8 + 2 * cq;
            *(float2*)(C + (size_t)row * 1024 + col) = make_float2(d[mt][nt][0], d[mt][nt][1]);
            *(float2*)(C + (size_t)(row + 8) * 1024 + col) = make_float2(d[mt][nt][2], d[mt][nt][3]);
        }
    }
    #undef LOAD_STAGE
}

// ---------------- 4) q head norm (tf32-rounded) ----------------
__global__ __launch_bounds__(256) void k_qnorm(const float* __restrict__ gamma) {
    int warp = threadIdx.x >> 5, lane = threadIdx.x & 31;
    int vec = blockIdx.x * 8 + warp;
    int row = vec >> 4;
    int qh  = vec & 15;
    float2 x = *(const float2*)(g_qproj + (size_t)row * 1024 + qh * 64 + lane * 2);
    float ss = x.x * x.x + x.y * x.y;
    #pragma unroll
    for (int o = 16; o; o >>= 1) ss += __shfl_xor_sync(0xffffffffu, ss, o);
    float inv = 1.0f / fmaxf(sqrtf(ss), 1e-12f);
    float2 g = *(const float2*)(gamma + qh * 64 + lane * 2);
    int b = row >> 11, n = row & 2047;
    float2 y;
    y.x = tf32r(x.x * inv * (g.x + 1.0f) * 8.0f);
    y.y = tf32r(x.y * inv * (g.y + 1.0f) * 8.0f);
    *(float2*)(g_q + ((((size_t)b * QH_ + qh) * N_ + n) * DH_) + lane * 2) = y;
}

// ---------------- 5) k head norm + v copy (tf32-rounded) ----------------
__global__ __launch_bounds__(256) void k_knorm(const float* __restrict__ gamma) {
    int warp = threadIdx.x >> 5, lane = threadIdx.x & 31;
    int vec = blockIdx.x * 8 + warp;
    int row = vec >> 3;
    int h   = vec & 7;
    const float* base = g_kv + (size_t)row * 1024 + h * 64 + lane * 2;
    float2 kx = *(const float2*)base;
    float2 vx = *(const float2*)(base + 512);
    float ss = kx.x * kx.x + kx.y * kx.y;
    #pragma unroll
    for (int o = 16; o; o >>= 1) ss += __shfl_xor_sync(0xffffffffu, ss, o);
    float inv = 1.0f / fmaxf(sqrtf(ss), 1e-12f);
    float2 g = *(const float2*)(gamma + h * 64 + lane * 2);
    int b = row >> 11, n = row & 2047;
    size_t dst = (((size_t)b * H_ + h) * N_ + n) * DH_ + lane * 2;
    float2 ky;
    ky.x = tf32r(kx.x * inv * (g.x + 1.0f) * 8.0f);
    ky.y = tf32r(kx.y * inv * (g.y + 1.0f) * 8.0f);
    *(float2*)(g_k + dst) = ky;
    vx.x = tf32r(vx.x); vx.y = tf32r(vx.y);
    *(float2*)(g_v + dst) = vx;
}

// ---------------- 6) causal attention, tf32 mma, 64q x 64k tiles ----------------
// smem: Qs[64][68] | Ks[2][64][72] | Vs[2][64][72] | Ps[64][68]
#define QSS 68
#define KSS 72
#define OFF_KS (64 * QSS)
#define OFF_VS (OFF_KS + 2 * 64 * KSS)
#define OFF_PS (OFF_VS + 2 * 64 * KSS)
#define ATT_SMEM ((OFF_PS + 64 * QSS) * 4)

__global__ __launch_bounds__(256) void k_attn_mma() {
    extern __shared__ float sm[];
    float* Qs = sm;
    float* Ps = sm + OFF_PS;
    const uint32_t sb = smem_u32(sm);

    int bqh = blockIdx.y;
    int it  = gridDim.x - 1 - blockIdx.x;
    int b = bqh >> 4, qh = bqh & 15, h = qh >> 1;

    const float* Qg = g_q + (((size_t)bqh) * N_ + it * 64) * DH_;
    const float* Kg = g_k + ((size_t)(b * H_ + h)) * N_ * DH_;
    const float* Vg = g_v + ((size_t)(b * H_ + h)) * N_ * DH_;

    const int t = threadIdx.x, wid = t >> 5, lane = t & 31;
    const int wm = wid & 3, wn = wid >> 2;     // warp grid 4(m) x 2(n)
    const int r = lane >> 2, cq = lane & 3;
    const int row0 = wm * 16 + r;

    // load Q tile (sync)
    #pragma unroll
    for (int rep = 0; rep < 4; rep++) {
        int slot = rep * 256 + t;
        int i = slot >> 4, d4 = (slot & 15) * 4;
        *(float4*)&Qs[i * QSS + d4] = *(const float4*)(Qg + i * 64 + d4);
    }

    // cp.async K/V tile loader: 4 chunks K + 4 chunks V per thread
    #define LOADKV(s, jt_) do { \
        uint32_t kb = sb + (OFF_KS + (s) * 64 * KSS) * 4; \
        uint32_t vb = sb + (OFF_VS + (s) * 64 * KSS) * 4; \
        _Pragma("unroll") \
        for (int rep = 0; rep < 4; rep++) { \
            int slot = rep * 256 + t; \
            int j = slot >> 4, d4 = (slot & 15) * 4; \
            cpa16(kb + (j * KSS + d4) * 4, Kg + (size_t)((jt_) * 64 + j) * 64 + d4); \
            cpa16(vb + (j * KSS + d4) * 4, Vg + (size_t)((jt_) * 64 + j) * 64 + d4); \
        } \
        CP_COMMIT(); \
    } while (0)

    LOADKV(0, 0);

    float o[4][4];
    #pragma unroll
    for (int nt = 0; nt < 4; nt++)
        #pragma unroll
        for (int v = 0; v < 4; v++) o[nt][v] = 0.0f;
    float srow = 0.0f, srow8 = 0.0f;

    for (int jt = 0; jt <= it; jt++) {
        int s = jt & 1;
        if (jt < it) { LOADKV(s ^ 1, jt + 1); CP_WAIT(1); }
        else         { CP_WAIT(0); }
        __syncthreads();

        const float* K_ = sm + OFF_KS + s * 64 * KSS;
        const float* V_ = sm + OFF_VS + s * 64 * KSS;

        // ---- S = Q K^T ----
        float dS[4][4];
        #pragma unroll
        for (int nt = 0; nt < 4; nt++)
            #pragma unroll
            for (int v = 0; v < 4; v++) dS[nt][v] = 0.0f;

        #pragma unroll
        for (int c = 0; c < 8; c++) {
            int kc = c * 8 + cq;
            float a[4], bfr[4][2];
            a[0] = Qs[row0 * QSS + kc];
            a[1] = Qs[(row0 + 8) * QSS + kc];
            a[2] = Qs[row0 * QSS + kc + 4];
            a[3] = Qs[(row0 + 8) * QSS + kc + 4];
            #pragma unroll
            for (int nt = 0; nt < 4; nt++) {
                int n = wn * 32 + nt * 8 + r;
                bfr[nt][0] = K_[n * KSS + kc];
                bfr[nt][1] = K_[n * KSS + kc + 4];
            }
            #pragma unroll
            for (int nt = 0; nt < 4; nt++) mma8(dS[nt], a, bfr[nt]);
        }

        // ---- softcap + exp + causal mask, stage P to smem (tf32) ----
        bool diag = (jt == it);
        int i0g = it * 64, j0g = jt * 64;
        #pragma unroll
        for (int nt = 0; nt < 4; nt++) {
            int colb = wn * 32 + nt * 8 + 2 * cq;
            #pragma unroll
            for (int v = 0; v < 4; v++) {
                int rr = i0g + row0 + ((v >= 2) ? 8 : 0);
                int cc = j0g + colb + (v & 1);
                float val = tanhf(dS[nt][v] * (1.0f / 50.0f)) * 6.25f;
                float p = __expf(val);
                if (diag && cc > rr) p = 0.0f;
                dS[nt][v] = tf32r(p);
            }
            *(float2*)&Ps[row0 * QSS + colb]       = make_float2(dS[nt][0], dS[nt][1]);
            *(float2*)&Ps[(row0 + 8) * QSS + colb] = make_float2(dS[nt][2], dS[nt][3]);
        }
        __syncthreads();

        // ---- O += P V (row sums ride along on A-fragments) ----
        #pragma unroll
        for (int c = 0; c < 8; c++) {
            int kc = c * 8 + cq;
            float a[4], bfr[4][2];
            a[0] = Ps[row0 * QSS + kc];
            a[1] = Ps[(row0 + 8) * QSS + kc];
            a[2] = Ps[row0 * QSS + kc + 4];
            a[3] = Ps[(row0 + 8) * QSS + kc + 4];
            srow  += a[0] + a[2];
            srow8 += a[1] + a[3];
            #pragma unroll
            for (int nt = 0; nt < 4; nt++) {
                int n = wn * 32 + nt * 8 + r;
                bfr[nt][0] = V_[kc * KSS + n];
                bfr[nt][1] = V_[(kc + 4) * KSS + n];
            }
            #pragma unroll
            for (int nt = 0; nt < 4; nt++) mma8(o[nt], a, bfr[nt]);
        }
        __syncthreads();   // protect Ps/K/V before next iteration overwrites
    }

    // row-sum reduce across the 4 cq lanes (both wn warps computed identical sums)
    srow  += __shfl_xor_sync(0xffffffffu, srow, 1);
    srow  += __shfl_xor_sync(0xffffffffu, srow, 2);
    srow8 += __shfl_xor_sync(0xffffffffu, srow8, 1);
    srow8 += __shfl_xor_sync(0xffffffffu, srow8, 2);
    float inv  = 1.0f / srow;
    float inv8 = 1.0f / srow8;

    float* Og = g_o + (((size_t)bqh) * N_ + it * 64) * DH_;
    #pragma unroll
    for (int nt = 0; nt < 4; nt++) {
        int colb = wn * 32 + nt * 8 + 2 * cq;
        *(float2*)(Og + (size_t)row0 * 64 + colb) =
            make_float2(o[nt][0] * inv, o[nt][1] * inv);
        *(float2*)(Og + (size_t)(row0 + 8) * 64 + colb) =
            make_float2(o[nt][2] * inv8, o[nt][3] * inv8);
    }
    #undef LOADKV
}

// ---------------- 7) group-sum combine (tf32-rounded) ----------------
__global__ __launch_bounds__(256) void k_combine() {
    int s4 = blockIdx.x * 256 + threadIdx.x;
    int col = (s4 & 127) * 4;
    int row = s4 >> 7;
    int h = col >> 6, dh = col & 63;
    int b = row >> 11, n = row & 2047;
    const float* o1 = g_o + ((((size_t)b * QH_ + 2 * h) * N_ + n) * DH_ + dh);
    const float* o2 = o1 + (size_t)N_ * DH_;
    float4 a = *(const float4*)o1, c = *(const float4*)o2;
    float4 y = make_float4(tf32r(a.x + c.x), tf32r(a.y + c.y),
                           tf32r(a.z + c.z), tf32r(a.w + c.w));
    *(float4*)(g_oc + (size_t)row * 512 + col) = y;
}

// ---------------- launch ----------------
extern "C" void kernel_launch(void* const* d_in, const int* in_sizes, int n_in,
                              void* d_out, int out_size) {
    const float* tokens  = (const float*)d_in[0];
    const float* norm_w  = (const float*)d_in[1];
    const float* Wq      = (const float*)d_in[2];
    const float* Wkv     = (const float*)d_in[3];
    const float* Wout    = (const float*)d_in[4];
    const float* q_gamma = (const float*)d_in[5];
    const float* k_gamma = (const float*)d_in[6];
    float* out = (float*)d_out;

    static float *Wqr_p = nullptr, *Wkvr_p = nullptr, *Wor_p = nullptr;
    static float *xn_p = nullptr, *oc_p = nullptr, *qproj_p = nullptr, *kv_p = nullptr;
    if (!Wqr_p) {   // first call is the non-captured correctness run
        cudaGetSymbolAddress((void**)&Wqr_p, g_Wqr);
        cudaGetSymbolAddress((void**)&Wkvr_p, g_Wkvr);
        cudaGetSymbolAddress((void**)&Wor_p, g_Wor);
        cudaGetSymbolAddress((void**)&xn_p, g_xn);
        cudaGetSymbolAddress((void**)&oc_p, g_oc);
        cudaGetSymbolAddress((void**)&qproj_p, g_qproj);
        cudaGetSymbolAddress((void**)&kv_p, g_kv);
        cudaFuncSetAttribute(k_attn_mma, cudaFuncAttributeMaxDynamicSharedMemorySize, ATT_SMEM);
    }

    k_rmsnorm<<<ROWS, 256>>>(tokens, norm_w);
    k_round<<<1024, 256>>>((const float4*)Wq,   (float4*)Wqr_p,  262144);
    k_round<<<1024, 256>>>((const float4*)Wkv,  (float4*)Wkvr_p, 262144);
    k_round<<<512,  256>>>((const float4*)Wout, (float4*)Wor_p,  131072);
    k_mmagemm<<<dim3(8, 32), 256>>>(xn_p, Wqr_p,  qproj_p, 1024);
    k_mmagemm<<<dim3(8, 32), 256>>>(xn_p, Wkvr_p, kv_p,    1024);
    k_qnorm<<<8192, 256>>>(q_gamma);
    k_knorm<<<4096, 256>>>(k_gamma);
    k_attn_mma<<<dim3(32, 32), 256, ATT_SMEM>>>();
    k_combine<<<2048, 256>>>();
    k_mmagemm<<<dim3(8, 32), 256>>>(oc_p, Wor_p, out, 512);
}

// round 5
// speedup vs baseline: 2.9300x; 1.2337x over previous
#include <cuda_runtime.h>
#include <cuda_fp16.h>
#include <cstdint>
#include <math.h>

#define B_  2
#define N_  2048
#define D_  1024
#define H_  8
#define QH_ 16
#define DH_ 64
#define ROWS (B_*N_)   // 4096

// ---------------- scratch (device globals; no allocs) ----------------
__device__ __half g_xnh[(size_t)ROWS * D_];          // rmsnormed tokens (fp16)
__device__ float  g_qproj[(size_t)ROWS * 1024];      // x @ Wq
__device__ float  g_kv[(size_t)ROWS * 1024];         // x @ Wkv
__device__ float  g_q[(size_t)B_ * QH_ * N_ * DH_];  // [b][qh][n][dh] tf32
__device__ float  g_k[(size_t)B_ * H_  * N_ * DH_];  // [b][h][n][dh] tf32
__device__ float  g_v[(size_t)B_ * H_  * N_ * DH_];  // [b][h][n][dh] tf32
__device__ float  g_o[(size_t)B_ * QH_ * N_ * DH_];  // per-qhead attn out
__device__ __half g_och[(size_t)ROWS * (H_ * DH_)];  // group-summed (fp16)
__device__ __half g_Wqh [(size_t)1024 * 1024];       // fp16 Wq  [k][n]
__device__ __half g_Wkvh[(size_t)1024 * 1024];       // fp16 Wkv [k][n]
__device__ __half g_Woh [(size_t)512 * 1024];        // fp16 Wout[k][n]

// ---------------- helpers ----------------
__device__ __forceinline__ float tf32r(float x) {
    uint32_t u;
    asm("cvt.rna.tf32.f32 %0, %1;" : "=r"(u) : "f"(x));
    return __uint_as_float(u);
}
__device__ __forceinline__ uint32_t smem_u32(const void* p) {
    uint32_t a;
    asm("{ .reg .u64 t; cvta.to.shared.u64 t, %1; cvt.u32.u64 %0, t; }" : "=r"(a) : "l"(p));
    return a;
}
__device__ __forceinline__ void cpa16(uint32_t dst, const void* src) {
    asm volatile("cp.async.ca.shared.global [%0], [%1], 16;" :: "r"(dst), "l"(src));
}
#define CP_COMMIT() asm volatile("cp.async.commit_group;" ::: "memory")
#define CP_WAIT(n)  asm volatile("cp.async.wait_group %0;" :: "n"(n) : "memory")

// tf32 mma m16n8k8 (attention)
__device__ __forceinline__ void mma8(float* d, const float* a, const float* b) {
    asm volatile("mma.sync.aligned.m16n8k8.row.col.f32.tf32.tf32.f32 "
                 "{%0,%1,%2,%3}, {%4,%5,%6,%7}, {%8,%9}, {%0,%1,%2,%3};"
                 : "+f"(d[0]), "+f"(d[1]), "+f"(d[2]), "+f"(d[3])
                 : "r"(__float_as_uint(a[0])), "r"(__float_as_uint(a[1])),
                   "r"(__float_as_uint(a[2])), "r"(__float_as_uint(a[3])),
                   "r"(__float_as_uint(b[0])), "r"(__float_as_uint(b[1])));
}
// fp16 mma m16n8k16 (projections)
__device__ __forceinline__ void mmah(float* d, const uint32_t* a, const uint32_t* b) {
    asm volatile("mma.sync.aligned.m16n8k16.row.col.f32.f16.f16.f32 "
                 "{%0,%1,%2,%3}, {%4,%5,%6,%7}, {%8,%9}, {%0,%1,%2,%3};"
                 : "+f"(d[0]), "+f"(d[1]), "+f"(d[2]), "+f"(d[3])
                 : "r"(a[0]), "r"(a[1]), "r"(a[2]), "r"(a[3]),
                   "r"(b[0]), "r"(b[1]));
}
__device__ __forceinline__ void ldsm_x4(uint32_t* r, uint32_t addr) {
    asm volatile("ldmatrix.sync.aligned.m8n8.x4.shared.b16 {%0,%1,%2,%3}, [%4];"
                 : "=r"(r[0]), "=r"(r[1]), "=r"(r[2]), "=r"(r[3]) : "r"(addr));
}
__device__ __forceinline__ void ldsm_x2t(uint32_t* r, uint32_t addr) {
    asm volatile("ldmatrix.sync.aligned.m8n8.x2.trans.shared.b16 {%0,%1}, [%2];"
                 : "=r"(r[0]), "=r"(r[1]) : "r"(addr));
}

// ---------------- 1) RMSNorm -> fp16 ----------------
__global__ __launch_bounds__(256) void k_rmsnorm(const float* __restrict__ x,
                                                 const float* __restrict__ w) {
    int row = blockIdx.x;
    const float4* xr = (const float4*)(x + (size_t)row * D_);
    float4 xv = xr[threadIdx.x];
    float ss = xv.x*xv.x + xv.y*xv.y + xv.z*xv.z + xv.w*xv.w;
    #pragma unroll
    for (int o = 16; o; o >>= 1) ss += __shfl_xor_sync(0xffffffffu, ss, o);
    __shared__ float sred[8];
    int wid = threadIdx.x >> 5, lid = threadIdx.x & 31;
    if (lid == 0) sred[wid] = ss;
    __syncthreads();
    if (wid == 0) {
        float v = (lid < 8) ? sred[lid] : 0.0f;
        #pragma unroll
        for (int o = 4; o; o >>= 1) v += __shfl_xor_sync(0xffffffffu, v, o);
        if (lid == 0) sred[0] = v;
    }
    __syncthreads();
    float s = rsqrtf(sred[0] * (1.0f / D_) + 1.192092896e-7f);
    float4 wv = ((const float4*)w)[threadIdx.x];
    __half2* dst = (__half2*)(g_xnh + (size_t)row * D_ + threadIdx.x * 4);
    dst[0] = __floats2half2_rn(xv.x * s * wv.x, xv.y * s * wv.y);
    dst[1] = __floats2half2_rn(xv.z * s * wv.z, xv.w * s * wv.w);
}

// ---------------- 2) f32 -> f16 weight convert ----------------
__global__ __launch_bounds__(256) void k_tohalf(const float4* __restrict__ src,
                                                __half2* __restrict__ dst, int n4) {
    int i = blockIdx.x * 256 + threadIdx.x;
    if (i < n4) {
        float4 v = src[i];
        dst[2 * i]     = __floats2half2_rn(v.x, v.y);
        dst[2 * i + 1] = __floats2half2_rn(v.z, v.w);
    }
}

// ---------------- 3) fp16 mma GEMM: C[m][n] = sum_k A[m][k] W[k][n] ----------------
// CTA 128x128, 8 warps (2x4), warp tile 64x32, K-chunk 32, cp.async double buffer.
#define HAS 40                 // A smem stride (halves): 80B -> LDSM conflict-free
#define HBS 136                // B smem stride (halves): 272B -> conflict-free
#define HASZ (128 * HAS)       // 5120 halves
#define HBSZ (32 * HBS)        // 4352 halves
#define HSTG (HASZ + HBSZ)     // 9472 halves / stage

__global__ __launch_bounds__(256) void k_gemmh(const __half* __restrict__ A,
                                               const __half* __restrict__ W,
                                               float* __restrict__ C, int K) {
    __shared__ __half hs[2 * HSTG];
    const int t = threadIdx.x, wid = t >> 5, lane = t & 31;
    const int wm = wid >> 2, wn = wid & 3;
    const int r = lane >> 2, cq = lane & 3;
    const int m0 = blockIdx.y * 128, n0 = blockIdx.x * 128;
    const uint32_t sb = smem_u32(hs);

    // cp.async slots: 2 A chunks + 2 B chunks (16B each) per thread per stage
    const int qa0 = t, qa1 = t + 256;
    const int ar0 = qa0 >> 2, ac0 = (qa0 & 3) * 8;
    const int ar1 = qa1 >> 2, ac1 = (qa1 & 3) * 8;
    const int br0 = qa0 >> 4, bc0 = (qa0 & 15) * 8;
    const int br1 = qa1 >> 4, bc1 = (qa1 & 15) * 8;

    // ldmatrix lane geometry
    const int lrow = lane & 7, lt = lane >> 3;        // A: tile 0..3
    const int aR = (lt & 1) * 8 + lrow;               // row-in-16 block
    const int aC = (lt >> 1) * 8;                     // col 0 or 8
    const int lb = lane & 15, bt = lb >> 3, brw = lb & 7;  // B: tile 0..1

    float d[4][4][4];
    #pragma unroll
    for (int i = 0; i < 4; i++)
        #pragma unroll
        for (int j = 0; j < 4; j++)
            #pragma unroll
            for (int v = 0; v < 4; v++) d[i][j][v] = 0.0f;

    const int nc = K >> 5;

    #define LOAD_STAGE(s, c) do { \
        uint32_t ab = sb + (s) * (HSTG * 2); \
        uint32_t bb = ab + HASZ * 2; \
        int k0 = (c) << 5; \
        cpa16(ab + (ar0 * HAS + ac0) * 2, A + (size_t)(m0 + ar0) * K + k0 + ac0); \
        cpa16(ab + (ar1 * HAS + ac1) * 2, A + (size_t)(m0 + ar1) * K + k0 + ac1); \
        cpa16(bb + (br0 * HBS + bc0) * 2, W + (size_t)(k0 + br0) * 1024 + n0 + bc0); \
        cpa16(bb + (br1 * HBS + bc1) * 2, W + (size_t)(k0 + br1) * 1024 + n0 + bc1); \
        CP_COMMIT(); \
    } while (0)

    LOAD_STAGE(0, 0);

    for (int c = 0; c < nc; c++) {
        int s = c & 1;
        if (c + 1 < nc) { LOAD_STAGE(s ^ 1, c + 1); CP_WAIT(1); }
        else            { CP_WAIT(0); }
        __syncthreads();

        uint32_t ab = sb + s * (HSTG * 2);
        uint32_t bb = ab + HASZ * 2;
        #pragma unroll
        for (int ks = 0; ks < 2; ks++) {
            uint32_t a[4][4], b[4][2];
            #pragma unroll
            for (int mt = 0; mt < 4; mt++)
                ldsm_x4(a[mt], ab + ((wm * 64 + mt * 16 + aR) * HAS + ks * 16 + aC) * 2);
            #pragma unroll
            for (int nt = 0; nt < 4; nt++)
                ldsm_x2t(b[nt], bb + ((ks * 16 + bt * 8 + brw) * HBS + wn * 32 + nt * 8) * 2);
            #pragma unroll
            for (int mt = 0; mt < 4; mt++)
                #pragma unroll
                for (int nt = 0; nt < 4; nt++) mmah(d[mt][nt], a[mt], b[nt]);
        }
        __syncthreads();
    }

    #pragma unroll
    for (int mt = 0; mt < 4; mt++) {
        int row = m0 + wm * 64 + mt * 16 + r;
        #pragma unroll
        for (int nt = 0; nt < 4; nt++) {
            int col = n0 + wn * 32 + nt * 8 + 2 * cq;
            *(float2*)(C + (size_t)row * 1024 + col) = make_float2(d[mt][nt][0], d[mt][nt][1]);
            *(float2*)(C + (size_t)(row + 8) * 1024 + col) = make_float2(d[mt][nt][2], d[mt][nt][3]);
        }
    }
    #undef LOAD_STAGE
}

// ---------------- 4) q head norm (tf32-rounded) ----------------
__global__ __launch_bounds__(256) void k_qnorm(const float* __restrict__ gamma) {
    int warp = threadIdx.x >> 5, lane = threadIdx.x & 31;
    int vec = blockIdx.x * 8 + warp;
    int row = vec >> 4;
    int qh  = vec & 15;
    float2 x = *(const float2*)(g_qproj + (size_t)row * 1024 + qh * 64 + lane * 2);
    float ss = x.x * x.x + x.y * x.y;
    #pragma unroll
    for (int o = 16; o; o >>= 1) ss += __shfl_xor_sync(0xffffffffu, ss, o);
    float inv = 1.0f / fmaxf(sqrtf(ss), 1e-12f);
    float2 g = *(const float2*)(gamma + qh * 64 + lane * 2);
    int b = row >> 11, n = row & 2047;
    float2 y;
    y.x = tf32r(x.x * inv * (g.x + 1.0f) * 8.0f);
    y.y = tf32r(x.y * inv * (g.y + 1.0f) * 8.0f);
    *(float2*)(g_q + ((((size_t)b * QH_ + qh) * N_ + n) * DH_) + lane * 2) = y;
}

// ---------------- 5) k head norm + v copy (tf32-rounded) ----------------
__global__ __launch_bounds__(256) void k_knorm(const float* __restrict__ gamma) {
    int warp = threadIdx.x >> 5, lane = threadIdx.x & 31;
    int vec = blockIdx.x * 8 + warp;
    int row = vec >> 3;
    int h   = vec & 7;
    const float* base = g_kv + (size_t)row * 1024 + h * 64 + lane * 2;
    float2 kx = *(const float2*)base;
    float2 vx = *(const float2*)(base + 512);
    float ss = kx.x * kx.x + kx.y * kx.y;
    #pragma unroll
    for (int o = 16; o; o >>= 1) ss += __shfl_xor_sync(0xffffffffu, ss, o);
    float inv = 1.0f / fmaxf(sqrtf(ss), 1e-12f);
    float2 g = *(const float2*)(gamma + h * 64 + lane * 2);
    int b = row >> 11, n = row & 2047;
    size_t dst = (((size_t)b * H_ + h) * N_ + n) * DH_ + lane * 2;
    float2 ky;
    ky.x = tf32r(kx.x * inv * (g.x + 1.0f) * 8.0f);
    ky.y = tf32r(kx.y * inv * (g.y + 1.0f) * 8.0f);
    *(float2*)(g_k + dst) = ky;
    vx.x = tf32r(vx.x); vx.y = tf32r(vx.y);
    *(float2*)(g_v + dst) = vx;
}

// ---------------- 6) causal attention, tf32 mma, 64q x 64k tiles ----------------
#define QSS 68
#define KSS 72
#define OFF_KS (64 * QSS)
#define OFF_VS (OFF_KS + 2 * 64 * KSS)
#define OFF_PS (OFF_VS + 2 * 64 * KSS)
#define ATT_SMEM ((OFF_PS + 64 * QSS) * 4)

__global__ __launch_bounds__(256) void k_attn_mma() {
    extern __shared__ float sm[];
    float* Qs = sm;
    float* Ps = sm + OFF_PS;
    const uint32_t sb = smem_u32(sm);

    int bqh = blockIdx.y;
    int it  = gridDim.x - 1 - blockIdx.x;
    int b = bqh >> 4, qh = bqh & 15, h = qh >> 1;

    const float* Qg = g_q + (((size_t)bqh) * N_ + it * 64) * DH_;
    const float* Kg = g_k + ((size_t)(b * H_ + h)) * N_ * DH_;
    const float* Vg = g_v + ((size_t)(b * H_ + h)) * N_ * DH_;

    const int t = threadIdx.x, wid = t >> 5, lane = t & 31;
    const int wm = wid & 3, wn = wid >> 2;
    const int r = lane >> 2, cq = lane & 3;
    const int row0 = wm * 16 + r;

    #pragma unroll
    for (int rep = 0; rep < 4; rep++) {
        int slot = rep * 256 + t;
        int i = slot >> 4, d4 = (slot & 15) * 4;
        *(float4*)&Qs[i * QSS + d4] = *(const float4*)(Qg + i * 64 + d4);
    }

    #define LOADKV(s, jt_) do { \
        uint32_t kb = sb + (OFF_KS + (s) * 64 * KSS) * 4; \
        uint32_t vb = sb + (OFF_VS + (s) * 64 * KSS) * 4; \
        _Pragma("unroll") \
        for (int rep = 0; rep < 4; rep++) { \
            int slot = rep * 256 + t; \
            int j = slot >> 4, d4 = (slot & 15) * 4; \
            cpa16(kb + (j * KSS + d4) * 4, Kg + (size_t)((jt_) * 64 + j) * 64 + d4); \
            cpa16(vb + (j * KSS + d4) * 4, Vg + (size_t)((jt_) * 64 + j) * 64 + d4); \
        } \
        CP_COMMIT(); \
    } while (0)

    LOADKV(0, 0);

    float o[4][4];
    #pragma unroll
    for (int nt = 0; nt < 4; nt++)
        #pragma unroll
        for (int v = 0; v < 4; v++) o[nt][v] = 0.0f;
    float srow = 0.0f, srow8 = 0.0f;

    for (int jt = 0; jt <= it; jt++) {
        int s = jt & 1;
        if (jt < it) { LOADKV(s ^ 1, jt + 1); CP_WAIT(1); }
        else         { CP_WAIT(0); }
        __syncthreads();

        const float* K_ = sm + OFF_KS + s * 64 * KSS;
        const float* V_ = sm + OFF_VS + s * 64 * KSS;

        float dS[4][4];
        #pragma unroll
        for (int nt = 0; nt < 4; nt++)
            #pragma unroll
            for (int v = 0; v < 4; v++) dS[nt][v] = 0.0f;

        #pragma unroll
        for (int c = 0; c < 8; c++) {
            int kc = c * 8 + cq;
            float a[4], bfr[4][2];
            a[0] = Qs[row0 * QSS + kc];
            a[1] = Qs[(row0 + 8) * QSS + kc];
            a[2] = Qs[row0 * QSS + kc + 4];
            a[3] = Qs[(row0 + 8) * QSS + kc + 4];
            #pragma unroll
            for (int nt = 0; nt < 4; nt++) {
                int n = wn * 32 + nt * 8 + r;
                bfr[nt][0] = K_[n * KSS + kc];
                bfr[nt][1] = K_[n * KSS + kc + 4];
            }
            #pragma unroll
            for (int nt = 0; nt < 4; nt++) mma8(dS[nt], a, bfr[nt]);
        }

        bool diag = (jt == it);
        int i0g = it * 64, j0g = jt * 64;
        #pragma unroll
        for (int nt = 0; nt < 4; nt++) {
            int colb = wn * 32 + nt * 8 + 2 * cq;
            #pragma unroll
            for (int v = 0; v < 4; v++) {
                int rr = i0g + row0 + ((v >= 2) ? 8 : 0);
                int cc = j0g + colb + (v & 1);
                float val = tanhf(dS[nt][v] * (1.0f / 50.0f)) * 6.25f;
                float p = __expf(val);
                if (diag && cc > rr) p = 0.0f;
                dS[nt][v] = tf32r(p);
            }
            *(float2*)&Ps[row0 * QSS + colb]       = make_float2(dS[nt][0], dS[nt][1]);
            *(float2*)&Ps[(row0 + 8) * QSS + colb] = make_float2(dS[nt][2], dS[nt][3]);
        }
        __syncthreads();

        #pragma unroll
        for (int c = 0; c < 8; c++) {
            int kc = c * 8 + cq;
            float a[4], bfr[4][2];
            a[0] = Ps[row0 * QSS + kc];
            a[1] = Ps[(row0 + 8) * QSS + kc];
            a[2] = Ps[row0 * QSS + kc + 4];
            a[3] = Ps[(row0 + 8) * QSS + kc + 4];
            srow  += a[0] + a[2];
            srow8 += a[1] + a[3];
            #pragma unroll
            for (int nt = 0; nt < 4; nt++) {
                int n = wn * 32 + nt * 8 + r;
                bfr[nt][0] = V_[kc * KSS + n];
                bfr[nt][1] = V_[(kc + 4) * KSS + n];
            }
            #pragma unroll
            for (int nt = 0; nt < 4; nt++) mma8(o[nt], a, bfr[nt]);
        }
        __syncthreads();
    }

    srow  += __shfl_xor_sync(0xffffffffu, srow, 1);
    srow  += __shfl_xor_sync(0xffffffffu, srow, 2);
    srow8 += __shfl_xor_sync(0xffffffffu, srow8, 1);
    srow8 += __shfl_xor_sync(0xffffffffu, srow8, 2);
    float inv  = 1.0f / srow;
    float inv8 = 1.0f / srow8;

    float* Og = g_o + (((size_t)bqh) * N_ + it * 64) * DH_;
    #pragma unroll
    for (int nt = 0; nt < 4; nt++) {
        int colb = wn * 32 + nt * 8 + 2 * cq;
        *(float2*)(Og + (size_t)row0 * 64 + colb) =
            make_float2(o[nt][0] * inv, o[nt][1] * inv);
        *(float2*)(Og + (size_t)(row0 + 8) * 64 + colb) =
            make_float2(o[nt][2] * inv8, o[nt][3] * inv8);
    }
    #undef LOADKV
}

// ---------------- 7) group-sum combine -> fp16 ----------------
__global__ __launch_bounds__(256) void k_combine() {
    int s4 = blockIdx.x * 256 + threadIdx.x;
    int col = (s4 & 127) * 4;
    int row = s4 >> 7;
    int h = col >> 6, dh = col & 63;
    int b = row >> 11, n = row & 2047;
    const float* o1 = g_o + ((((size_t)b * QH_ + 2 * h) * N_ + n) * DH_ + dh);
    const float* o2 = o1 + (size_t)N_ * DH_;
    float4 a = *(const float4*)o1, c = *(const float4*)o2;
    __half2* dst = (__half2*)(g_och + (size_t)row * 512 + col);
    dst[0] = __floats2half2_rn(a.x + c.x, a.y + c.y);
    dst[1] = __floats2half2_rn(a.z + c.z, a.w + c.w);
}

// ---------------- launch ----------------
extern "C" void kernel_launch(void* const* d_in, const int* in_sizes, int n_in,
                              void* d_out, int out_size) {
    const float* tokens  = (const float*)d_in[0];
    const float* norm_w  = (const float*)d_in[1];
    const float* Wq      = (const float*)d_in[2];
    const float* Wkv     = (const float*)d_in[3];
    const float* Wout    = (const float*)d_in[4];
    const float* q_gamma = (const float*)d_in[5];
    const float* k_gamma = (const float*)d_in[6];
    float* out = (float*)d_out;

    static __half *Wqh_p = nullptr, *Wkvh_p = nullptr, *Woh_p = nullptr;
    static __half *xnh_p = nullptr, *och_p = nullptr;
    static float *qproj_p = nullptr, *kv_p = nullptr;
    if (!Wqh_p) {   // first call is the non-captured correctness run
        cudaGetSymbolAddress((void**)&Wqh_p, g_Wqh);
        cudaGetSymbolAddress((void**)&Wkvh_p, g_Wkvh);
        cudaGetSymbolAddress((void**)&Woh_p, g_Woh);
        cudaGetSymbolAddress((void**)&xnh_p, g_xnh);
        cudaGetSymbolAddress((void**)&och_p, g_och);
        cudaGetSymbolAddress((void**)&qproj_p, g_qproj);
        cudaGetSymbolAddress((void**)&kv_p, g_kv);
        cudaFuncSetAttribute(k_attn_mma, cudaFuncAttributeMaxDynamicSharedMemorySize, ATT_SMEM);
    }

    k_rmsnorm<<<ROWS, 256>>>(tokens, norm_w);
    k_tohalf<<<1024, 256>>>((const float4*)Wq,   (__half2*)Wqh_p,  262144);
    k_tohalf<<<1024, 256>>>((const float4*)Wkv,  (__half2*)Wkvh_p, 262144);
    k_tohalf<<<512,  256>>>((const float4*)Wout, (__half2*)Woh_p,  131072);
    k_gemmh<<<dim3(8, 32), 256>>>(xnh_p, Wqh_p,  qproj_p, 1024);
    k_gemmh<<<dim3(8, 32), 256>>>(xnh_p, Wkvh_p, kv_p,    1024);
    k_qnorm<<<8192, 256>>>(q_gamma);
    k_knorm<<<4096, 256>>>(k_gamma);
    k_attn_mma<<<dim3(32, 32), 256, ATT_SMEM>>>();
    k_combine<<<2048, 256>>>();
    k_gemmh<<<dim3(8, 32), 256>>>(och_p, Woh_p, out, 512);
}

// round 6
// speedup vs baseline: 4.4269x; 1.5109x over previous
#include <cuda_runtime.h>
#include <cuda_fp16.h>
#include <cstdint>
#include <math.h>

#define B_  2
#define N_  2048
#define D_  1024
#define H_  8
#define QH_ 16
#define DH_ 64
#define ROWS (B_*N_)   // 4096

// ---------------- scratch (device globals; no allocs) ----------------
__device__ __half g_xnh[(size_t)ROWS * D_];          // rmsnormed tokens (fp16)
__device__ float  g_qproj[(size_t)ROWS * 1024];      // x @ Wq
__device__ float  g_kv[(size_t)ROWS * 1024];         // x @ Wkv
__device__ __half g_qh[(size_t)B_ * QH_ * N_ * DH_]; // [b][qh][n][dh] fp16
__device__ __half g_kh[(size_t)B_ * H_  * N_ * DH_]; // [b][h][n][dh] fp16
__device__ __half g_vh[(size_t)B_ * H_  * N_ * DH_]; // [b][h][n][dh] fp16
__device__ float  g_o[(size_t)B_ * QH_ * N_ * DH_];  // per-qhead attn out
__device__ __half g_och[(size_t)ROWS * (H_ * DH_)];  // group-summed (fp16)
__device__ __half g_Wqh [(size_t)1024 * 1024];       // fp16 Wq  [k][n]
__device__ __half g_Wkvh[(size_t)1024 * 1024];       // fp16 Wkv [k][n]
__device__ __half g_Woh [(size_t)512 * 1024];        // fp16 Wout[k][n]

// ---------------- helpers ----------------
__device__ __forceinline__ uint32_t smem_u32(const void* p) {
    uint32_t a;
    asm("{ .reg .u64 t; cvta.to.shared.u64 t, %1; cvt.u32.u64 %0, t; }" : "=r"(a) : "l"(p));
    return a;
}
__device__ __forceinline__ void cpa16(uint32_t dst, const void* src) {
    asm volatile("cp.async.ca.shared.global [%0], [%1], 16;" :: "r"(dst), "l"(src));
}
#define CP_COMMIT() asm volatile("cp.async.commit_group;" ::: "memory")
#define CP_WAIT(n)  asm volatile("cp.async.wait_group %0;" :: "n"(n) : "memory")

// fp16 mma m16n8k16
__device__ __forceinline__ void mmah(float* d, const uint32_t* a, const uint32_t* b) {
    asm volatile("mma.sync.aligned.m16n8k16.row.col.f32.f16.f16.f32 "
                 "{%0,%1,%2,%3}, {%4,%5,%6,%7}, {%8,%9}, {%0,%1,%2,%3};"
                 : "+f"(d[0]), "+f"(d[1]), "+f"(d[2]), "+f"(d[3])
                 : "r"(a[0]), "r"(a[1]), "r"(a[2]), "r"(a[3]),
                   "r"(b[0]), "r"(b[1]));
}
__device__ __forceinline__ void ldsm_x4(uint32_t* r, uint32_t addr) {
    asm volatile("ldmatrix.sync.aligned.m8n8.x4.shared.b16 {%0,%1,%2,%3}, [%4];"
                 : "=r"(r[0]), "=r"(r[1]), "=r"(r[2]), "=r"(r[3]) : "r"(addr));
}
__device__ __forceinline__ void ldsm_x2(uint32_t* r, uint32_t addr) {
    asm volatile("ldmatrix.sync.aligned.m8n8.x2.shared.b16 {%0,%1}, [%2];"
                 : "=r"(r[0]), "=r"(r[1]) : "r"(addr));
}
__device__ __forceinline__ void ldsm_x2t(uint32_t* r, uint32_t addr) {
    asm volatile("ldmatrix.sync.aligned.m8n8.x2.trans.shared.b16 {%0,%1}, [%2];"
                 : "=r"(r[0]), "=r"(r[1]) : "r"(addr));
}

// ---------------- 1) RMSNorm -> fp16 ----------------
__global__ __launch_bounds__(256) void k_rmsnorm(const float* __restrict__ x,
                                                 const float* __restrict__ w) {
    int row = blockIdx.x;
    const float4* xr = (const float4*)(x + (size_t)row * D_);
    float4 xv = xr[threadIdx.x];
    float ss = xv.x*xv.x + xv.y*xv.y + xv.z*xv.z + xv.w*xv.w;
    #pragma unroll
    for (int o = 16; o; o >>= 1) ss += __shfl_xor_sync(0xffffffffu, ss, o);
    __shared__ float sred[8];
    int wid = threadIdx.x >> 5, lid = threadIdx.x & 31;
    if (lid == 0) sred[wid] = ss;
    __syncthreads();
    if (wid == 0) {
        float v = (lid < 8) ? sred[lid] : 0.0f;
        #pragma unroll
        for (int o = 4; o; o >>= 1) v += __shfl_xor_sync(0xffffffffu, v, o);
        if (lid == 0) sred[0] = v;
    }
    __syncthreads();
    float s = rsqrtf(sred[0] * (1.0f / D_) + 1.192092896e-7f);
    float4 wv = ((const float4*)w)[threadIdx.x];
    __half2* dst = (__half2*)(g_xnh + (size_t)row * D_ + threadIdx.x * 4);
    dst[0] = __floats2half2_rn(xv.x * s * wv.x, xv.y * s * wv.y);
    dst[1] = __floats2half2_rn(xv.z * s * wv.z, xv.w * s * wv.w);
}

// ---------------- 2) fused f32 -> f16 weight convert (all three W) ----------------
__global__ __launch_bounds__(256) void k_tohalf3(const float4* __restrict__ Wq,
                                                 const float4* __restrict__ Wkv,
                                                 const float4* __restrict__ Wo) {
    int i = blockIdx.x * 256 + threadIdx.x;   // < 655360
    const float4* src; __half2* dst; int j;
    if (i < 262144)      { src = Wq;  dst = (__half2*)g_Wqh;  j = i; }
    else if (i < 524288) { src = Wkv; dst = (__half2*)g_Wkvh; j = i - 262144; }
    else                 { src = Wo;  dst = (__half2*)g_Woh;  j = i - 524288; }
    float4 v = src[j];
    dst[2 * j]     = __floats2half2_rn(v.x, v.y);
    dst[2 * j + 1] = __floats2half2_rn(v.z, v.w);
}

// ---------------- 3) fp16 mma GEMM (proven in R5) ----------------
#define HAS 40
#define HBS 136
#define HASZ (128 * HAS)
#define HBSZ (32 * HBS)
#define HSTG (HASZ + HBSZ)

__global__ __launch_bounds__(256) void k_gemmh(const __half* __restrict__ A,
                                               const __half* __restrict__ W,
                                               float* __restrict__ C, int K) {
    __shared__ __half hs[2 * HSTG];
    const int t = threadIdx.x, wid = t >> 5, lane = t & 31;
    const int wm = wid >> 2, wn = wid & 3;
    const int r = lane >> 2, cq = lane & 3;
    const int m0 = blockIdx.y * 128, n0 = blockIdx.x * 128;
    const uint32_t sb = smem_u32(hs);

    const int qa0 = t, qa1 = t + 256;
    const int ar0 = qa0 >> 2, ac0 = (qa0 & 3) * 8;
    const int ar1 = qa1 >> 2, ac1 = (qa1 & 3) * 8;
    const int br0 = qa0 >> 4, bc0 = (qa0 & 15) * 8;
    const int br1 = qa1 >> 4, bc1 = (qa1 & 15) * 8;

    const int lrow = lane & 7, lt = lane >> 3;
    const int aR = (lt & 1) * 8 + lrow;
    const int aC = (lt >> 1) * 8;
    const int lb = lane & 15, bt = lb >> 3, brw = lb & 7;

    float d[4][4][4];
    #pragma unroll
    for (int i = 0; i < 4; i++)
        #pragma unroll
        for (int j = 0; j < 4; j++)
            #pragma unroll
            for (int v = 0; v < 4; v++) d[i][j][v] = 0.0f;

    const int nc = K >> 5;

    #define LOAD_STAGE(s, c) do { \
        uint32_t ab = sb + (s) * (HSTG * 2); \
        uint32_t bb = ab + HASZ * 2; \
        int k0 = (c) << 5; \
        cpa16(ab + (ar0 * HAS + ac0) * 2, A + (size_t)(m0 + ar0) * K + k0 + ac0); \
        cpa16(ab + (ar1 * HAS + ac1) * 2, A + (size_t)(m0 + ar1) * K + k0 + ac1); \
        cpa16(bb + (br0 * HBS + bc0) * 2, W + (size_t)(k0 + br0) * 1024 + n0 + bc0); \
        cpa16(bb + (br1 * HBS + bc1) * 2, W + (size_t)(k0 + br1) * 1024 + n0 + bc1); \
        CP_COMMIT(); \
    } while (0)

    LOAD_STAGE(0, 0);

    for (int c = 0; c < nc; c++) {
        int s = c & 1;
        if (c + 1 < nc) { LOAD_STAGE(s ^ 1, c + 1); CP_WAIT(1); }
        else            { CP_WAIT(0); }
        __syncthreads();

        uint32_t ab = sb + s * (HSTG * 2);
        uint32_t bb = ab + HASZ * 2;
        #pragma unroll
        for (int ks = 0; ks < 2; ks++) {
            uint32_t a[4][4], b[4][2];
            #pragma unroll
            for (int mt = 0; mt < 4; mt++)
                ldsm_x4(a[mt], ab + ((wm * 64 + mt * 16 + aR) * HAS + ks * 16 + aC) * 2);
            #pragma unroll
            for (int nt = 0; nt < 4; nt++)
                ldsm_x2t(b[nt], bb + ((ks * 16 + bt * 8 + brw) * HBS + wn * 32 + nt * 8) * 2);
            #pragma unroll
            for (int mt = 0; mt < 4; mt++)
                #pragma unroll
                for (int nt = 0; nt < 4; nt++) mmah(d[mt][nt], a[mt], b[nt]);
        }
        __syncthreads();
    }

    #pragma unroll
    for (int mt = 0; mt < 4; mt++) {
        int row = m0 + wm * 64 + mt * 16 + r;
        #pragma unroll
        for (int nt = 0; nt < 4; nt++) {
            int col = n0 + wn * 32 + nt * 8 + 2 * cq;
            *(float2*)(C + (size_t)row * 1024 + col) = make_float2(d[mt][nt][0], d[mt][nt][1]);
            *(float2*)(C + (size_t)(row + 8) * 1024 + col) = make_float2(d[mt][nt][2], d[mt][nt][3]);
        }
    }
    #undef LOAD_STAGE
}

// ---------------- 4) q head norm -> fp16 ----------------
__global__ __launch_bounds__(256) void k_qnorm(const float* __restrict__ gamma) {
    int warp = threadIdx.x >> 5, lane = threadIdx.x & 31;
    int vec = blockIdx.x * 8 + warp;
    int row = vec >> 4;
    int qh  = vec & 15;
    float2 x = *(const float2*)(g_qproj + (size_t)row * 1024 + qh * 64 + lane * 2);
    float ss = x.x * x.x + x.y * x.y;
    #pragma unroll
    for (int o = 16; o; o >>= 1) ss += __shfl_xor_sync(0xffffffffu, ss, o);
    float inv = 1.0f / fmaxf(sqrtf(ss), 1e-12f);
    float2 g = *(const float2*)(gamma + qh * 64 + lane * 2);
    int b = row >> 11, n = row & 2047;
    *(__half2*)(g_qh + ((((size_t)b * QH_ + qh) * N_ + n) * DH_) + lane * 2) =
        __floats2half2_rn(x.x * inv * (g.x + 1.0f) * 8.0f,
                          x.y * inv * (g.y + 1.0f) * 8.0f);
}

// ---------------- 5) k head norm + v copy -> fp16 ----------------
__global__ __launch_bounds__(256) void k_knorm(const float* __restrict__ gamma) {
    int warp = threadIdx.x >> 5, lane = threadIdx.x & 31;
    int vec = blockIdx.x * 8 + warp;
    int row = vec >> 3;
    int h   = vec & 7;
    const float* base = g_kv + (size_t)row * 1024 + h * 64 + lane * 2;
    float2 kx = *(const float2*)base;
    float2 vx = *(const float2*)(base + 512);
    float ss = kx.x * kx.x + kx.y * kx.y;
    #pragma unroll
    for (int o = 16; o; o >>= 1) ss += __shfl_xor_sync(0xffffffffu, ss, o);
    float inv = 1.0f / fmaxf(sqrtf(ss), 1e-12f);
    float2 g = *(const float2*)(gamma + h * 64 + lane * 2);
    int b = row >> 11, n = row & 2047;
    size_t dst = (((size_t)b * H_ + h) * N_ + n) * DH_ + lane * 2;
    *(__half2*)(g_kh + dst) = __floats2half2_rn(kx.x * inv * (g.x + 1.0f) * 8.0f,
                                                kx.y * inv * (g.y + 1.0f) * 8.0f);
    *(__half2*)(g_vh + dst) = __floats2half2_rn(vx.x, vx.y);
}

// ---------------- 6) causal attention, fp16 mma + ldmatrix, 64q x 64k ----------------
// smem (halves, stride 72): Qh[64] | Kh[2][64] | Vh[2][64] | Ph[64]
#define AQS 72
#define OFFK 4608
#define OFFV (OFFK + 2 * 4608)
#define OFFP (OFFV + 2 * 4608)
#define ATTH_SMEM ((OFFP + 4608) * 2)   // 55296 bytes

__global__ __launch_bounds__(256) void k_attn_h() {
    extern __shared__ __half sh[];
    __half* Qh = sh;
    __half* Ph = sh + OFFP;
    const uint32_t sb = smem_u32(sh);

    int bqh = blockIdx.y;
    int it  = gridDim.x - 1 - blockIdx.x;
    int b = bqh >> 4, qh = bqh & 15, h = qh >> 1;

    const __half* Qg = g_qh + (((size_t)bqh) * N_ + it * 64) * DH_;
    const __half* Kg = g_kh + ((size_t)(b * H_ + h)) * N_ * DH_;
    const __half* Vg = g_vh + ((size_t)(b * H_ + h)) * N_ * DH_;

    const int t = threadIdx.x, wid = t >> 5, lane = t & 31;
    const int wm = wid & 3, wn = wid >> 2;     // 4(m) x 2(n) warps
    const int r = lane >> 2, cq = lane & 3;
    const int row0 = wm * 16 + r;
    const int lrow = lane & 7, lt = lane >> 3;
    const int aR = (lt & 1) * 8 + lrow, aC = (lt >> 1) * 8;
    const int lb = lane & 15, bt = lb >> 3, brw = lb & 7;

    const uint32_t qb = sb;                       // Q base (bytes)
    const uint32_t pb = sb + OFFP * 2;            // P base

    // load Q tile (sync, 2 uint4 per thread)
    #pragma unroll
    for (int rep = 0; rep < 2; rep++) {
        int slot = rep * 256 + t;
        int i = slot >> 3, d8 = (slot & 7) * 8;
        *(uint4*)&Qh[i * AQS + d8] = *(const uint4*)(Qg + i * 64 + d8);
    }

    #define LOADKV(s, jt_) do { \
        uint32_t kb_ = sb + (OFFK + (s) * 4608) * 2; \
        uint32_t vb_ = sb + (OFFV + (s) * 4608) * 2; \
        _Pragma("unroll") \
        for (int rep = 0; rep < 2; rep++) { \
            int slot = rep * 256 + t; \
            int j = slot >> 3, d8 = (slot & 7) * 8; \
            cpa16(kb_ + (j * AQS + d8) * 2, Kg + (size_t)((jt_) * 64 + j) * 64 + d8); \
            cpa16(vb_ + (j * AQS + d8) * 2, Vg + (size_t)((jt_) * 64 + j) * 64 + d8); \
        } \
        CP_COMMIT(); \
    } while (0)

    LOADKV(0, 0);

    float o[4][4];
    #pragma unroll
    for (int nt = 0; nt < 4; nt++)
        #pragma unroll
        for (int v = 0; v < 4; v++) o[nt][v] = 0.0f;
    float srow = 0.0f, srow8 = 0.0f;

    for (int jt = 0; jt <= it; jt++) {
        int s = jt & 1;
        if (jt < it) { LOADKV(s ^ 1, jt + 1); CP_WAIT(1); }
        else         { CP_WAIT(0); }
        __syncthreads();

        uint32_t kb = sb + (OFFK + s * 4608) * 2;
        uint32_t vb = sb + (OFFV + s * 4608) * 2;

        // ---- S = Q K^T (fp16 mma, fp32 accum) ----
        float dS[4][4];
        #pragma unroll
        for (int nt = 0; nt < 4; nt++)
            #pragma unroll
            for (int v = 0; v < 4; v++) dS[nt][v] = 0.0f;

        #pragma unroll
        for (int ks = 0; ks < 4; ks++) {
            uint32_t a[4];
            ldsm_x4(a, qb + ((wm * 16 + aR) * AQS + ks * 16 + aC) * 2);
            #pragma unroll
            for (int nt = 0; nt < 4; nt++) {
                uint32_t bfr[2];
                ldsm_x2(bfr, kb + ((wn * 32 + nt * 8 + brw) * AQS + ks * 16 + bt * 8) * 2);
                mmah(dS[nt], a, bfr);
            }
        }

        // ---- softcap + exp + causal mask -> P (fp16 smem) ----
        bool diag = (jt == it);
        int i0g = it * 64, j0g = jt * 64;
        #pragma unroll
        for (int nt = 0; nt < 4; nt++) {
            int colb = wn * 32 + nt * 8 + 2 * cq;
            float p[4];
            #pragma unroll
            for (int v = 0; v < 4; v++) {
                int rr = i0g + row0 + ((v >= 2) ? 8 : 0);
                int cc = j0g + colb + (v & 1);
                float val = tanhf(dS[nt][v] * (1.0f / 50.0f)) * 6.25f;
                p[v] = __expf(val);
                if (diag && cc > rr) p[v] = 0.0f;
            }
            *(__half2*)&Ph[row0 * AQS + colb]       = __floats2half2_rn(p[0], p[1]);
            *(__half2*)&Ph[(row0 + 8) * AQS + colb] = __floats2half2_rn(p[2], p[3]);
        }
        __syncthreads();

        // ---- O += P V (row sums ride on A fragments) ----
        #pragma unroll
        for (int c = 0; c < 4; c++) {
            uint32_t a[4];
            ldsm_x4(a, pb + ((wm * 16 + aR) * AQS + c * 16 + aC) * 2);
            float2 f0 = __half22float2(*(__half2*)&a[0]);
            float2 f2 = __half22float2(*(__half2*)&a[2]);
            float2 f1 = __half22float2(*(__half2*)&a[1]);
            float2 f3 = __half22float2(*(__half2*)&a[3]);
            srow  += f0.x + f0.y + f2.x + f2.y;
            srow8 += f1.x + f1.y + f3.x + f3.y;
            #pragma unroll
            for (int nt = 0; nt < 4; nt++) {
                uint32_t bfr[2];
                ldsm_x2t(bfr, vb + ((c * 16 + bt * 8 + brw) * AQS + wn * 32 + nt * 8) * 2);
                mmah(o[nt], a, bfr);
            }
        }
        __syncthreads();   // protect Ph/K/V before next iteration overwrites
    }

    srow  += __shfl_xor_sync(0xffffffffu, srow, 1);
    srow  += __shfl_xor_sync(0xffffffffu, srow, 2);
    srow8 += __shfl_xor_sync(0xffffffffu, srow8, 1);
    srow8 += __shfl_xor_sync(0xffffffffu, srow8, 2);
    float inv  = 1.0f / srow;
    float inv8 = 1.0f / srow8;

    float* Og = g_o + (((size_t)bqh) * N_ + it * 64) * DH_;
    #pragma unroll
    for (int nt = 0; nt < 4; nt++) {
        int colb = wn * 32 + nt * 8 + 2 * cq;
        *(float2*)(Og + (size_t)row0 * 64 + colb) =
            make_float2(o[nt][0] * inv, o[nt][1] * inv);
        *(float2*)(Og + (size_t)(row0 + 8) * 64 + colb) =
            make_float2(o[nt][2] * inv8, o[nt][3] * inv8);
    }
    #undef LOADKV
}

// ---------------- 7) group-sum combine -> fp16 ----------------
__global__ __launch_bounds__(256) void k_combine() {
    int s4 = blockIdx.x * 256 + threadIdx.x;
    int col = (s4 & 127) * 4;
    int row = s4 >> 7;
    int h = col >> 6, dh = col & 63;
    int b = row >> 11, n = row & 2047;
    const float* o1 = g_o + ((((size_t)b * QH_ + 2 * h) * N_ + n) * DH_ + dh);
    const float* o2 = o1 + (size_t)N_ * DH_;
    float4 a = *(const float4*)o1, c = *(const float4*)o2;
    __half2* dst = (__half2*)(g_och + (size_t)row * 512 + col);
    dst[0] = __floats2half2_rn(a.x + c.x, a.y + c.y);
    dst[1] = __floats2half2_rn(a.z + c.z, a.w + c.w);
}

// ---------------- launch ----------------
extern "C" void kernel_launch(void* const* d_in, const int* in_sizes, int n_in,
                              void* d_out, int out_size) {
    const float* tokens  = (const float*)d_in[0];
    const float* norm_w  = (const float*)d_in[1];
    const float* Wq      = (const float*)d_in[2];
    const float* Wkv     = (const float*)d_in[3];
    const float* Wout    = (const float*)d_in[4];
    const float* q_gamma = (const float*)d_in[5];
    const float* k_gamma = (const float*)d_in[6];
    float* out = (float*)d_out;

    static __half *Wqh_p = nullptr, *Wkvh_p = nullptr, *Woh_p = nullptr;
    static __half *xnh_p = nullptr, *och_p = nullptr;
    static float *qproj_p = nullptr, *kv_p = nullptr;
    if (!Wqh_p) {   // first call is the non-captured correctness run
        cudaGetSymbolAddress((void**)&Wqh_p, g_Wqh);
        cudaGetSymbolAddress((void**)&Wkvh_p, g_Wkvh);
        cudaGetSymbolAddress((void**)&Woh_p, g_Woh);
        cudaGetSymbolAddress((void**)&xnh_p, g_xnh);
        cudaGetSymbolAddress((void**)&och_p, g_och);
        cudaGetSymbolAddress((void**)&qproj_p, g_qproj);
        cudaGetSymbolAddress((void**)&kv_p, g_kv);
        cudaFuncSetAttribute(k_attn_h, cudaFuncAttributeMaxDynamicSharedMemorySize, ATTH_SMEM);
    }

    k_rmsnorm<<<ROWS, 256>>>(tokens, norm_w);
    k_tohalf3<<<2560, 256>>>((const float4*)Wq, (const float4*)Wkv, (const float4*)Wout);
    k_gemmh<<<dim3(8, 32), 256>>>(xnh_p, Wqh_p,  qproj_p, 1024);
    k_gemmh<<<dim3(8, 32), 256>>>(xnh_p, Wkvh_p, kv_p,    1024);
    k_qnorm<<<8192, 256>>>(q_gamma);
    k_knorm<<<4096, 256>>>(k_gamma);
    k_attn_h<<<dim3(32, 32), 256, ATTH_SMEM>>>();
    k_combine<<<2048, 256>>>();
    k_gemmh<<<dim3(8, 32), 256>>>(och_p, Woh_p, out, 512);
}